// round 1
// baseline (speedup 1.0000x reference)
#include <cuda_runtime.h>
#include <math_constants.h>

// Problem constants
#define B_  2
#define T_  2048
#define C_  1024
#define H_  16
#define D_  64
#define M_  (B_*T_)          // 4096 rows
#define BHTD (B_*H_*T_*D_)   // 4,194,304

// Scratch (device globals: allocation-free per harness rules)
__device__ float g_q[BHTD];
__device__ float g_k[BHTD];
__device__ float g_v[BHTD];
__device__ float g_y[B_*T_*C_];

// ---------------------------------------------------------------------------
// SGEMM: out[M,N] = A[M,K] * W[N,K]^T + bias[N]
// MODE 0: A = g_y (attention output), write row-major to `out`
// MODE 1: A = x, scatter columns into g_q/g_k/g_v with [B,H,T,D] layout
// 128x128 tile, BK=8, 256 threads, 8x8 micro-tile per thread.
// ---------------------------------------------------------------------------
template<int MODE>
__global__ void __launch_bounds__(256) sgemm_kernel(
    const float* __restrict__ A, const float* __restrict__ W,
    const float* __restrict__ bias, float* __restrict__ out,
    int N, int K)
{
    __shared__ float As[8][132];
    __shared__ float Bs[8][132];

    const int tid = threadIdx.x;
    const int m0 = blockIdx.y * 128;
    const int n0 = blockIdx.x * 128;
    const int tx = tid & 15;
    const int ty = tid >> 4;
    const int lrow = tid >> 1;          // 0..127
    const int lk   = (tid & 1) << 2;    // 0 or 4

    const float* Ain = (MODE == 0) ? (const float*)g_y : A;
    const float* Ap = Ain + (size_t)(m0 + lrow) * K + lk;
    const float* Wp = W   + (size_t)(n0 + lrow) * K + lk;

    float acc[8][8];
#pragma unroll
    for (int i = 0; i < 8; i++)
#pragma unroll
        for (int j = 0; j < 8; j++) acc[i][j] = 0.f;

    for (int k0 = 0; k0 < K; k0 += 8) {
        float4 av = *(const float4*)(Ap + k0);
        float4 bv = *(const float4*)(Wp + k0);
        __syncthreads();   // previous compute done before overwrite
        As[lk+0][lrow] = av.x; As[lk+1][lrow] = av.y;
        As[lk+2][lrow] = av.z; As[lk+3][lrow] = av.w;
        Bs[lk+0][lrow] = bv.x; Bs[lk+1][lrow] = bv.y;
        Bs[lk+2][lrow] = bv.z; Bs[lk+3][lrow] = bv.w;
        __syncthreads();
#pragma unroll
        for (int kk = 0; kk < 8; kk++) {
            float4 a0 = *(const float4*)&As[kk][ty*8];
            float4 a1 = *(const float4*)&As[kk][ty*8+4];
            float4 b0 = *(const float4*)&Bs[kk][tx*8];
            float4 b1 = *(const float4*)&Bs[kk][tx*8+4];
            float a[8] = {a0.x,a0.y,a0.z,a0.w,a1.x,a1.y,a1.z,a1.w};
            float b[8] = {b0.x,b0.y,b0.z,b0.w,b1.x,b1.y,b1.z,b1.w};
#pragma unroll
            for (int i = 0; i < 8; i++)
#pragma unroll
                for (int j = 0; j < 8; j++)
                    acc[i][j] = fmaf(a[i], b[j], acc[i][j]);
        }
    }

    float bvals[8];
#pragma unroll
    for (int j = 0; j < 8; j++) bvals[j] = bias[n0 + tx*8 + j];

    if (MODE == 0) {
#pragma unroll
        for (int i = 0; i < 8; i++) {
            int m = m0 + ty*8 + i;
            float4 o0, o1;
            o0.x = acc[i][0]+bvals[0]; o0.y = acc[i][1]+bvals[1];
            o0.z = acc[i][2]+bvals[2]; o0.w = acc[i][3]+bvals[3];
            o1.x = acc[i][4]+bvals[4]; o1.y = acc[i][5]+bvals[5];
            o1.z = acc[i][6]+bvals[6]; o1.w = acc[i][7]+bvals[7];
            *(float4*)&out[(size_t)m*N + n0 + tx*8]     = o0;
            *(float4*)&out[(size_t)m*N + n0 + tx*8 + 4] = o1;
        }
    } else {
        // Scatter into q/k/v [B,H,T,D]. A 128-col tile never straddles the
        // 1024 (q/k/v) boundary, and an 8-col run never straddles a head.
        int n = n0 + tx*8;
        int which = n >> 10;
        int h = (n & 1023) >> 6;
        int d = n & 63;
        float* dst = (which == 0) ? g_q : ((which == 1) ? g_k : g_v);
#pragma unroll
        for (int i = 0; i < 8; i++) {
            int m = m0 + ty*8 + i;
            int b = m >> 11;        // /2048
            int t = m & 2047;
            size_t base = ((size_t)(b*H_ + h)*T_ + t)*D_ + d;
            float4 o0, o1;
            o0.x = acc[i][0]+bvals[0]; o0.y = acc[i][1]+bvals[1];
            o0.z = acc[i][2]+bvals[2]; o0.w = acc[i][3]+bvals[3];
            o1.x = acc[i][4]+bvals[4]; o1.y = acc[i][5]+bvals[5];
            o1.z = acc[i][6]+bvals[6]; o1.w = acc[i][7]+bvals[7];
            *(float4*)&dst[base]     = o0;
            *(float4*)&dst[base + 4] = o1;
        }
    }
}

// ---------------------------------------------------------------------------
// RoPE applied in place to g_q and g_k.
// out[d]    = x[d]*cos(t*f_d)    - x[d+32]*sin(t*f_d)       (d < 32)
// out[d+32] = x[d+32]*cos(t*f_d) + x[d]*sin(t*f_d)
// f_d = 10000^(-d/32)
// ---------------------------------------------------------------------------
__global__ void rope_kernel()
{
    int idx = blockIdx.x * blockDim.x + threadIdx.x;   // B*H*T*32 threads
    int d  = idx & 31;
    int t  = (idx >> 5) & (T_ - 1);
    int bh = idx >> 16;                                 // / (2048*32)
    size_t base = ((size_t)bh * T_ + t) * D_;

    const float L2_10000_OVER_32 = 13.287712379549449f / 32.0f;
    float f = exp2f(-(float)d * L2_10000_OVER_32);
    float ang = (float)t * f;
    float s, c;
    sincosf(ang, &s, &c);

    float q1 = g_q[base + d], q2 = g_q[base + d + 32];
    g_q[base + d]      = q1*c - q2*s;
    g_q[base + d + 32] = q2*c + q1*s;
    float k1 = g_k[base + d], k2 = g_k[base + d + 32];
    g_k[base + d]      = k1*c - k2*s;
    g_k[base + d + 32] = k2*c + k1*s;
}

// ---------------------------------------------------------------------------
// Flash attention, fp32, causal. One block = 64 q-rows of one (b,h).
// 256 threads: ty=tid/16 owns 4 q-rows (ty*4..+3), tx=tid%16 owns cols
// {tx, tx+16, tx+32, tx+48} (interleaved so smem reads are conflict-light).
// Output written directly in [B,T,C] layout to g_y.
// ---------------------------------------------------------------------------
#define KPAD 68
#define ATTN_SMEM ((64*64*3 + 64*KPAD) * 4)

__global__ void __launch_bounds__(256) attn_kernel()
{
    extern __shared__ float smbuf[];
    float* Qs = smbuf;              // [64][64]
    float* Ks = Qs + 64*64;         // [64][KPAD]
    float* Vs = Ks + 64*KPAD;       // [64][64]
    float* Ps = Vs + 64*64;         // [64][64]

    const int qt  = blockIdx.x;
    const int bh  = blockIdx.y;
    const int tid = threadIdx.x;
    const int tx  = tid & 15;
    const int ty  = tid >> 4;
    const int r0  = ty * 4;

    const float* qb = g_q + ((size_t)bh * T_ + qt*64) * D_;
#pragma unroll
    for (int it = 0; it < 4; it++) {
        int f = tid + it*256;
        int r = f >> 4, dq = (f & 15) << 2;
        *(float4*)(Qs + r*64 + dq) = *(const float4*)(qb + r*64 + dq);
    }

    float m_i[4], l_i[4], o[4][4];
#pragma unroll
    for (int i = 0; i < 4; i++) {
        m_i[i] = -CUDART_INF_F;
        l_i[i] = 0.f;
#pragma unroll
        for (int j = 0; j < 4; j++) o[i][j] = 0.f;
    }

    for (int jt = 0; jt <= qt; jt++) {
        __syncthreads();   // prior PV reads done (and Q load for jt=0)
        const float* kb = g_k + ((size_t)bh * T_ + jt*64) * D_;
        const float* vb = g_v + ((size_t)bh * T_ + jt*64) * D_;
#pragma unroll
        for (int it = 0; it < 4; it++) {
            int f = tid + it*256;
            int r = f >> 4, dq = (f & 15) << 2;
            *(float4*)(Vs + r*64   + dq) = *(const float4*)(vb + r*64 + dq);
            *(float4*)(Ks + r*KPAD + dq) = *(const float4*)(kb + r*64 + dq);
        }
        __syncthreads();

        // S = Q K^T (64x64x64), 4x4 per thread
        float s[4][4];
#pragma unroll
        for (int i = 0; i < 4; i++)
#pragma unroll
            for (int j = 0; j < 4; j++) s[i][j] = 0.f;

#pragma unroll
        for (int dk = 0; dk < 64; dk += 4) {
            float4 qv[4], kv[4];
#pragma unroll
            for (int i = 0; i < 4; i++)
                qv[i] = *(const float4*)(Qs + (r0+i)*64 + dk);
#pragma unroll
            for (int j = 0; j < 4; j++)
                kv[j] = *(const float4*)(Ks + (tx + 16*j)*KPAD + dk);
#pragma unroll
            for (int i = 0; i < 4; i++)
#pragma unroll
                for (int j = 0; j < 4; j++) {
                    s[i][j] = fmaf(qv[i].x, kv[j].x, s[i][j]);
                    s[i][j] = fmaf(qv[i].y, kv[j].y, s[i][j]);
                    s[i][j] = fmaf(qv[i].z, kv[j].z, s[i][j]);
                    s[i][j] = fmaf(qv[i].w, kv[j].w, s[i][j]);
                }
        }

        // masked online softmax
        const bool diag = (jt == qt);
#pragma unroll
        for (int i = 0; i < 4; i++) {
            float vals[4];
            int qi = r0 + i;   // local q row; same-tile compare for causal
#pragma unroll
            for (int j = 0; j < 4; j++) {
                float v = s[i][j] * 0.125f;
                int kc = tx + 16*j;
                if (diag && kc > qi) v = -CUDART_INF_F;
                vals[j] = v;
            }
            float rm = fmaxf(fmaxf(vals[0], vals[1]), fmaxf(vals[2], vals[3]));
#pragma unroll
            for (int off = 8; off; off >>= 1)
                rm = fmaxf(rm, __shfl_xor_sync(0xffffffffu, rm, off));
            float mn   = fmaxf(m_i[i], rm);
            float corr = __expf(m_i[i] - mn);
            m_i[i] = mn;
            float rs = 0.f;
#pragma unroll
            for (int j = 0; j < 4; j++) {
                float p = __expf(vals[j] - mn);
                Ps[(r0+i)*64 + tx + 16*j] = p;
                rs += p;
            }
#pragma unroll
            for (int off = 8; off; off >>= 1)
                rs += __shfl_xor_sync(0xffffffffu, rs, off);
            l_i[i] = l_i[i]*corr + rs;
#pragma unroll
            for (int j = 0; j < 4; j++) o[i][j] *= corr;
        }
        __syncthreads();   // Ps visible

        // O += P V  (64x64x64)
#pragma unroll 4
        for (int kk = 0; kk < 64; kk++) {
            float vv[4];
#pragma unroll
            for (int j = 0; j < 4; j++) vv[j] = Vs[kk*64 + tx + 16*j];
#pragma unroll
            for (int i = 0; i < 4; i++) {
                float p = Ps[(r0+i)*64 + kk];
#pragma unroll
                for (int j = 0; j < 4; j++)
                    o[i][j] = fmaf(p, vv[j], o[i][j]);
            }
        }
    }

    // normalize + write to g_y in [B,T,C] layout
    int b = bh >> 4, h = bh & 15;
#pragma unroll
    for (int i = 0; i < 4; i++) {
        float inv = 1.0f / l_i[i];
        int t = qt*64 + r0 + i;
        size_t rowbase = ((size_t)b*T_ + t)*C_ + h*64;
#pragma unroll
        for (int j = 0; j < 4; j++)
            g_y[rowbase + tx + 16*j] = o[i][j] * inv;
    }
}

// ---------------------------------------------------------------------------
extern "C" void kernel_launch(void* const* d_in, const int* in_sizes, int n_in,
                              void* d_out, int out_size)
{
    const float* x      = (const float*)d_in[0];
    const float* W_attn = (const float*)d_in[1];
    const float* b_attn = (const float*)d_in[2];
    const float* W_proj = (const float*)d_in[3];
    const float* b_proj = (const float*)d_in[4];
    float* out = (float*)d_out;

    // 1) QKV projection, scattered straight into [B,H,T,D] q/k/v
    sgemm_kernel<1><<<dim3(3*C_/128, M_/128), 256>>>(x, W_attn, b_attn, nullptr, 3*C_, C_);

    // 2) RoPE in place on q,k
    rope_kernel<<<(B_*H_*T_*32)/256, 256>>>();

    // 3) causal flash attention -> g_y in [B,T,C]
    cudaFuncSetAttribute(attn_kernel, cudaFuncAttributeMaxDynamicSharedMemorySize, ATTN_SMEM);
    attn_kernel<<<dim3(T_/64, B_*H_), 256, ATTN_SMEM>>>();

    // 4) output projection + bias -> d_out
    sgemm_kernel<0><<<dim3(C_/128, M_/128), 256>>>(nullptr, W_proj, b_proj, out, C_, C_);
}

// round 5
// speedup vs baseline: 1.1366x; 1.1366x over previous
#include <cuda_runtime.h>
#include <cuda_bf16.h>
#include <math_constants.h>
#include <cstdint>

// Problem constants
#define B_  2
#define T_  2048
#define C_  1024
#define H_  16
#define D_  64
#define M_  (B_*T_)          // 4096 rows
#define BHTD (B_*H_*T_*D_)   // 4,194,304
#define KP_ (3*C_)           // 3072 split-K

// Scratch (device globals; accessed DIRECTLY from kernels — no symbol lookup)
__device__ float g_q[BHTD];
__device__ float g_k[BHTD];
__device__ float g_v[BHTD];
__device__ float g_y[B_*T_*C_];
__device__ __nv_bfloat16 g_xs[(size_t)M_ * KP_];     // x split     [4096,3072]
__device__ __nv_bfloat16 g_ws[(size_t)3*C_ * KP_];   // W_attn split [3072,3072]

// ---------------------------------------------------------------------------
// Split fp32 -> bf16 (hi, lo) packed along K'=3K=3072.
// A-side (x):      segments [hi, hi, lo]
// B-side (W_attn): segments [hi, lo, hi]
// dot over K' = hi*hi + hi*lo + lo*hi   (lo*lo ~ 2^-18 dropped)
// ---------------------------------------------------------------------------
__global__ void split_x_kernel(const float* __restrict__ src)
{
    int idx = blockIdx.x * blockDim.x + threadIdx.x;   // < M_*C_/4
    if (idx >= M_*C_/4) return;
    float4 v = ((const float4*)src)[idx];
    int r = idx >> 8;             // / (1024/4)
    int k = (idx & 255) * 4;
    float vv[4] = {v.x, v.y, v.z, v.w};
    size_t base = (size_t)r * KP_ + k;
#pragma unroll
    for (int i = 0; i < 4; i++) {
        __nv_bfloat16 hi = __float2bfloat16(vv[i]);
        __nv_bfloat16 lo = __float2bfloat16(vv[i] - __bfloat162float(hi));
        g_xs[base + i]          = hi;
        g_xs[base + C_ + i]     = hi;
        g_xs[base + 2*C_ + i]   = lo;
    }
}

__global__ void split_w_kernel(const float* __restrict__ src)
{
    int idx = blockIdx.x * blockDim.x + threadIdx.x;   // < 3*C_*C_/4
    if (idx >= 3*C_*C_/4) return;
    float4 v = ((const float4*)src)[idx];
    int r = idx >> 8;
    int k = (idx & 255) * 4;
    float vv[4] = {v.x, v.y, v.z, v.w};
    size_t base = (size_t)r * KP_ + k;
#pragma unroll
    for (int i = 0; i < 4; i++) {
        __nv_bfloat16 hi = __float2bfloat16(vv[i]);
        __nv_bfloat16 lo = __float2bfloat16(vv[i] - __bfloat162float(hi));
        g_ws[base + i]          = hi;
        g_ws[base + C_ + i]     = lo;
        g_ws[base + 2*C_ + i]   = hi;
    }
}

// ---------------------------------------------------------------------------
// QKV tensor-core GEMM: qkv[M,3072] = g_xs[M,3072] * g_ws[3072,3072]^T + bias
// scattered into g_q/g_k/g_v in [B,H,T,D] layout.
// 128x128 tile, BK=32 bf16, 256 threads (8 warps 4x2, warp tile 32x64),
// mma.sync.m16n8k16, double-buffered smem. Fragments loaded with explicit
// per-lane 32-bit LDS per the documented fragment layouts (no ldmatrix).
// SSTRIDE=40 elements (80B rows): lane groups map to disjoint bank quads.
// ---------------------------------------------------------------------------
#define SSTRIDE 40

__global__ void __launch_bounds__(256) mma_qkv(const float* __restrict__ bias)
{
    __shared__ __nv_bfloat16 As[2][128*SSTRIDE];
    __shared__ __nv_bfloat16 Bs[2][128*SSTRIDE];

    const int tid  = threadIdx.x;
    const int wid  = tid >> 5;
    const int lane = tid & 31;
    const int m0 = blockIdx.y * 128;
    const int n0 = blockIdx.x * 128;
    const int wm = (wid >> 1) * 32;
    const int wn = (wid & 1) * 64;
    const int lg = lane >> 2;        // 0..7 row group
    const int lt = (lane & 3) * 2;   // k pair offset

    const __nv_bfloat16* Ag = g_xs + (size_t)m0 * KP_;
    const __nv_bfloat16* Bg = g_ws + (size_t)n0 * KP_;

    float c[2][8][4];
#pragma unroll
    for (int i = 0; i < 2; i++)
#pragma unroll
        for (int j = 0; j < 8; j++)
#pragma unroll
            for (int r = 0; r < 4; r++) c[i][j][r] = 0.f;

    uint4 ra[2], rb[2];
    const int nt = KP_ / 32;   // 96

    // prologue: tile 0
#pragma unroll
    for (int i = 0; i < 2; i++) {
        int id = tid + 256*i, row = id >> 2, seg = id & 3;
        ra[i] = *(const uint4*)(Ag + (size_t)row*KP_ + seg*8);
        rb[i] = *(const uint4*)(Bg + (size_t)row*KP_ + seg*8);
    }
#pragma unroll
    for (int i = 0; i < 2; i++) {
        int id = tid + 256*i, row = id >> 2, seg = id & 3;
        *(uint4*)&As[0][row*SSTRIDE + seg*8] = ra[i];
        *(uint4*)&Bs[0][row*SSTRIDE + seg*8] = rb[i];
    }
    __syncthreads();

    for (int kt = 0; kt < nt; kt++) {
        const int buf = kt & 1;
        if (kt + 1 < nt) {
            const int k0 = (kt+1) * 32;
#pragma unroll
            for (int i = 0; i < 2; i++) {
                int id = tid + 256*i, row = id >> 2, seg = id & 3;
                ra[i] = *(const uint4*)(Ag + (size_t)row*KP_ + k0 + seg*8);
                rb[i] = *(const uint4*)(Bg + (size_t)row*KP_ + k0 + seg*8);
            }
        }

#pragma unroll
        for (int ks = 0; ks < 2; ks++) {
            const int k16 = ks * 16;
            // A fragments, explicit LDS.32 per documented m16n8k16 layout:
            // a0={A[g][2t],A[g][2t+1]}, a1=rows+8, a2=k+8, a3=rows+8,k+8
            unsigned int af[2][4];
#pragma unroll
            for (int mi = 0; mi < 2; mi++) {
                int r = wm + mi*16 + lg;
                int kc = k16 + lt;
                af[mi][0] = *(const unsigned int*)&As[buf][r*SSTRIDE + kc];
                af[mi][1] = *(const unsigned int*)&As[buf][(r+8)*SSTRIDE + kc];
                af[mi][2] = *(const unsigned int*)&As[buf][r*SSTRIDE + kc + 8];
                af[mi][3] = *(const unsigned int*)&As[buf][(r+8)*SSTRIDE + kc + 8];
            }
            // B fragments: b0={B[2t][g],B[2t+1][g]} = w[n=g][k=2t..+1], b1=k+8
            unsigned int bfr[8][2];
#pragma unroll
            for (int nj = 0; nj < 8; nj++) {
                int r = wn + nj*8 + lg;
                int kc = k16 + lt;
                bfr[nj][0] = *(const unsigned int*)&Bs[buf][r*SSTRIDE + kc];
                bfr[nj][1] = *(const unsigned int*)&Bs[buf][r*SSTRIDE + kc + 8];
            }
#pragma unroll
            for (int mi = 0; mi < 2; mi++)
#pragma unroll
                for (int nj = 0; nj < 8; nj++) {
                    asm volatile(
                        "mma.sync.aligned.m16n8k16.row.col.f32.bf16.bf16.f32 "
                        "{%0,%1,%2,%3}, {%4,%5,%6,%7}, {%8,%9}, {%0,%1,%2,%3};\n"
                        : "+f"(c[mi][nj][0]), "+f"(c[mi][nj][1]),
                          "+f"(c[mi][nj][2]), "+f"(c[mi][nj][3])
                        : "r"(af[mi][0]), "r"(af[mi][1]),
                          "r"(af[mi][2]), "r"(af[mi][3]),
                          "r"(bfr[nj][0]), "r"(bfr[nj][1]));
                }
        }

        if (kt + 1 < nt) {
            const int nbuf = buf ^ 1;
#pragma unroll
            for (int i = 0; i < 2; i++) {
                int id = tid + 256*i, row = id >> 2, seg = id & 3;
                *(uint4*)&As[nbuf][row*SSTRIDE + seg*8] = ra[i];
                *(uint4*)&Bs[nbuf][row*SSTRIDE + seg*8] = rb[i];
            }
            __syncthreads();
        }
    }

    // epilogue: scatter into g_q/g_k/g_v [B,H,T,D]
#pragma unroll
    for (int mi = 0; mi < 2; mi++) {
#pragma unroll
        for (int nj = 0; nj < 8; nj++) {
            int row = m0 + wm + mi*16 + (lane >> 2);
            int col = n0 + wn + nj*8 + (lane & 3)*2;
            float b0 = bias[col], b1 = bias[col+1];
            float2 v0 = { c[mi][nj][0] + b0, c[mi][nj][1] + b1 };
            float2 v1 = { c[mi][nj][2] + b0, c[mi][nj][3] + b1 };
            int which = col >> 10;
            int h = (col & 1023) >> 6;
            int d = col & 63;
            float* dst = (which == 0) ? g_q : ((which == 1) ? g_k : g_v);
            int b = row >> 11, t = row & 2047;
            size_t base0 = ((size_t)(b*H_ + h)*T_ + t    )*D_ + d;
            size_t base1 = ((size_t)(b*H_ + h)*T_ + t + 8)*D_ + d;
            *(float2*)&dst[base0] = v0;
            *(float2*)&dst[base1] = v1;
        }
    }
}

// ---------------------------------------------------------------------------
// Output projection: fp32 SGEMM (proven in R1).
// out[M,1024] = g_y[M,1024] * W_proj[1024,1024]^T + b_proj
// ---------------------------------------------------------------------------
__global__ void __launch_bounds__(256) sgemm_proj(
    const float* __restrict__ W, const float* __restrict__ bias,
    float* __restrict__ out)
{
    __shared__ float Asm[8][132];
    __shared__ float Bsm[8][132];

    const int tid = threadIdx.x;
    const int m0 = blockIdx.y * 128;
    const int n0 = blockIdx.x * 128;
    const int tx = tid & 15;
    const int ty = tid >> 4;
    const int lrow = tid >> 1;
    const int lk   = (tid & 1) << 2;
    const int K = C_, N = C_;

    const float* Ap = g_y + (size_t)(m0 + lrow) * K + lk;
    const float* Wp = W   + (size_t)(n0 + lrow) * K + lk;

    float acc[8][8];
#pragma unroll
    for (int i = 0; i < 8; i++)
#pragma unroll
        for (int j = 0; j < 8; j++) acc[i][j] = 0.f;

    for (int k0 = 0; k0 < K; k0 += 8) {
        float4 av = *(const float4*)(Ap + k0);
        float4 bv = *(const float4*)(Wp + k0);
        __syncthreads();
        Asm[lk+0][lrow] = av.x; Asm[lk+1][lrow] = av.y;
        Asm[lk+2][lrow] = av.z; Asm[lk+3][lrow] = av.w;
        Bsm[lk+0][lrow] = bv.x; Bsm[lk+1][lrow] = bv.y;
        Bsm[lk+2][lrow] = bv.z; Bsm[lk+3][lrow] = bv.w;
        __syncthreads();
#pragma unroll
        for (int kk = 0; kk < 8; kk++) {
            float4 a0 = *(const float4*)&Asm[kk][ty*8];
            float4 a1 = *(const float4*)&Asm[kk][ty*8+4];
            float4 b0 = *(const float4*)&Bsm[kk][tx*8];
            float4 b1 = *(const float4*)&Bsm[kk][tx*8+4];
            float a[8] = {a0.x,a0.y,a0.z,a0.w,a1.x,a1.y,a1.z,a1.w};
            float b[8] = {b0.x,b0.y,b0.z,b0.w,b1.x,b1.y,b1.z,b1.w};
#pragma unroll
            for (int i = 0; i < 8; i++)
#pragma unroll
                for (int j = 0; j < 8; j++)
                    acc[i][j] = fmaf(a[i], b[j], acc[i][j]);
        }
    }

    float bvals[8];
#pragma unroll
    for (int j = 0; j < 8; j++) bvals[j] = bias[n0 + tx*8 + j];

#pragma unroll
    for (int i = 0; i < 8; i++) {
        int m = m0 + ty*8 + i;
        float4 o0, o1;
        o0.x = acc[i][0]+bvals[0]; o0.y = acc[i][1]+bvals[1];
        o0.z = acc[i][2]+bvals[2]; o0.w = acc[i][3]+bvals[3];
        o1.x = acc[i][4]+bvals[4]; o1.y = acc[i][5]+bvals[5];
        o1.z = acc[i][6]+bvals[6]; o1.w = acc[i][7]+bvals[7];
        *(float4*)&out[(size_t)m*N + n0 + tx*8]     = o0;
        *(float4*)&out[(size_t)m*N + n0 + tx*8 + 4] = o1;
    }
}

// ---------------------------------------------------------------------------
// RoPE applied in place to g_q and g_k (proven in R1).
// ---------------------------------------------------------------------------
__global__ void rope_kernel()
{
    int idx = blockIdx.x * blockDim.x + threadIdx.x;   // B*H*T*32 threads
    int d  = idx & 31;
    int t  = (idx >> 5) & (T_ - 1);
    int bh = idx >> 16;
    size_t base = ((size_t)bh * T_ + t) * D_;

    const float L2_10000_OVER_32 = 13.287712379549449f / 32.0f;
    float f = exp2f(-(float)d * L2_10000_OVER_32);
    float ang = (float)t * f;
    float s, cc;
    sincosf(ang, &s, &cc);

    float q1 = g_q[base + d], q2 = g_q[base + d + 32];
    g_q[base + d]      = q1*cc - q2*s;
    g_q[base + d + 32] = q2*cc + q1*s;
    float k1 = g_k[base + d], k2 = g_k[base + d + 32];
    g_k[base + d]      = k1*cc - k2*s;
    g_k[base + d + 32] = k2*cc + k1*s;
}

// ---------------------------------------------------------------------------
// Flash attention, fp32, causal (proven in R1).
// ---------------------------------------------------------------------------
#define KPAD 68
#define ATTN_SMEM ((64*64*3 + 64*KPAD) * 4)

__global__ void __launch_bounds__(256) attn_kernel()
{
    extern __shared__ float smbuf[];
    float* Qs = smbuf;              // [64][64]
    float* Ks = Qs + 64*64;         // [64][KPAD]
    float* Vs = Ks + 64*KPAD;       // [64][64]
    float* Ps = Vs + 64*64;         // [64][64]

    const int qt  = blockIdx.x;
    const int bh  = blockIdx.y;
    const int tid = threadIdx.x;
    const int tx  = tid & 15;
    const int ty  = tid >> 4;
    const int r0  = ty * 4;

    const float* qb = g_q + ((size_t)bh * T_ + qt*64) * D_;
#pragma unroll
    for (int it = 0; it < 4; it++) {
        int f = tid + it*256;
        int r = f >> 4, dq = (f & 15) << 2;
        *(float4*)(Qs + r*64 + dq) = *(const float4*)(qb + r*64 + dq);
    }

    float m_i[4], l_i[4], o[4][4];
#pragma unroll
    for (int i = 0; i < 4; i++) {
        m_i[i] = -CUDART_INF_F;
        l_i[i] = 0.f;
#pragma unroll
        for (int j = 0; j < 4; j++) o[i][j] = 0.f;
    }

    for (int jt = 0; jt <= qt; jt++) {
        __syncthreads();
        const float* kb = g_k + ((size_t)bh * T_ + jt*64) * D_;
        const float* vb = g_v + ((size_t)bh * T_ + jt*64) * D_;
#pragma unroll
        for (int it = 0; it < 4; it++) {
            int f = tid + it*256;
            int r = f >> 4, dq = (f & 15) << 2;
            *(float4*)(Vs + r*64   + dq) = *(const float4*)(vb + r*64 + dq);
            *(float4*)(Ks + r*KPAD + dq) = *(const float4*)(kb + r*64 + dq);
        }
        __syncthreads();

        float s[4][4];
#pragma unroll
        for (int i = 0; i < 4; i++)
#pragma unroll
            for (int j = 0; j < 4; j++) s[i][j] = 0.f;

#pragma unroll
        for (int dk = 0; dk < 64; dk += 4) {
            float4 qv[4], kv[4];
#pragma unroll
            for (int i = 0; i < 4; i++)
                qv[i] = *(const float4*)(Qs + (r0+i)*64 + dk);
#pragma unroll
            for (int j = 0; j < 4; j++)
                kv[j] = *(const float4*)(Ks + (tx + 16*j)*KPAD + dk);
#pragma unroll
            for (int i = 0; i < 4; i++)
#pragma unroll
                for (int j = 0; j < 4; j++) {
                    s[i][j] = fmaf(qv[i].x, kv[j].x, s[i][j]);
                    s[i][j] = fmaf(qv[i].y, kv[j].y, s[i][j]);
                    s[i][j] = fmaf(qv[i].z, kv[j].z, s[i][j]);
                    s[i][j] = fmaf(qv[i].w, kv[j].w, s[i][j]);
                }
        }

        const bool diag = (jt == qt);
#pragma unroll
        for (int i = 0; i < 4; i++) {
            float vals[4];
            int qi = r0 + i;
#pragma unroll
            for (int j = 0; j < 4; j++) {
                float v = s[i][j] * 0.125f;
                int kc = tx + 16*j;
                if (diag && kc > qi) v = -CUDART_INF_F;
                vals[j] = v;
            }
            float rm = fmaxf(fmaxf(vals[0], vals[1]), fmaxf(vals[2], vals[3]));
#pragma unroll
            for (int off = 8; off; off >>= 1)
                rm = fmaxf(rm, __shfl_xor_sync(0xffffffffu, rm, off));
            float mn   = fmaxf(m_i[i], rm);
            float corr = __expf(m_i[i] - mn);
            m_i[i] = mn;
            float rs = 0.f;
#pragma unroll
            for (int j = 0; j < 4; j++) {
                float p = __expf(vals[j] - mn);
                Ps[(r0+i)*64 + tx + 16*j] = p;
                rs += p;
            }
#pragma unroll
            for (int off = 8; off; off >>= 1)
                rs += __shfl_xor_sync(0xffffffffu, rs, off);
            l_i[i] = l_i[i]*corr + rs;
#pragma unroll
            for (int j = 0; j < 4; j++) o[i][j] *= corr;
        }
        __syncthreads();

#pragma unroll 4
        for (int kk = 0; kk < 64; kk++) {
            float vv[4];
#pragma unroll
            for (int j = 0; j < 4; j++) vv[j] = Vs[kk*64 + tx + 16*j];
#pragma unroll
            for (int i = 0; i < 4; i++) {
                float p = Ps[(r0+i)*64 + kk];
#pragma unroll
                for (int j = 0; j < 4; j++)
                    o[i][j] = fmaf(p, vv[j], o[i][j]);
            }
        }
    }

    int b = bh >> 4, h = bh & 15;
#pragma unroll
    for (int i = 0; i < 4; i++) {
        float inv = 1.0f / l_i[i];
        int t = qt*64 + r0 + i;
        size_t rowbase = ((size_t)b*T_ + t)*C_ + h*64;
#pragma unroll
        for (int j = 0; j < 4; j++)
            g_y[rowbase + tx + 16*j] = o[i][j] * inv;
    }
}

// ---------------------------------------------------------------------------
extern "C" void kernel_launch(void* const* d_in, const int* in_sizes, int n_in,
                              void* d_out, int out_size)
{
    const float* x      = (const float*)d_in[0];
    const float* W_attn = (const float*)d_in[1];
    const float* b_attn = (const float*)d_in[2];
    const float* W_proj = (const float*)d_in[3];
    const float* b_proj = (const float*)d_in[4];
    float* out = (float*)d_out;

    // 0) split x and W_attn into bf16 hi/lo packings (direct global writes)
    split_x_kernel<<<(M_*C_/4 + 255)/256, 256>>>(x);
    split_w_kernel<<<(3*C_*C_/4 + 255)/256, 256>>>(W_attn);

    // 1) QKV projection (tensor cores), scattered into [B,H,T,D] q/k/v
    mma_qkv<<<dim3(3*C_/128, M_/128), 256>>>(b_attn);

    // 2) RoPE in place on q,k
    rope_kernel<<<(B_*H_*T_*32)/256, 256>>>();

    // 3) causal flash attention -> g_y in [B,T,C]
    cudaFuncSetAttribute(attn_kernel, cudaFuncAttributeMaxDynamicSharedMemorySize, ATTN_SMEM);
    attn_kernel<<<dim3(T_/64, B_*H_), 256, ATTN_SMEM>>>();

    // 4) output projection (fp32, proven)
    sgemm_proj<<<dim3(C_/128, M_/128), 256>>>(W_proj, b_proj, out);
}

// round 6
// speedup vs baseline: 1.6925x; 1.4891x over previous
#include <cuda_runtime.h>
#include <cuda_bf16.h>
#include <math_constants.h>
#include <cstdint>

// Problem constants
#define B_  2
#define T_  2048
#define C_  1024
#define H_  16
#define D_  64
#define M_  (B_*T_)          // 4096 rows
#define BHTD (B_*H_*T_*D_)
#define KP_ (3*C_)           // 3072 split-K

// Scratch (device globals, referenced directly from kernels)
__device__ float g_q[BHTD];
__device__ float g_k[BHTD];
__device__ float g_v[BHTD];
__device__ __nv_bfloat16 g_xs[(size_t)M_ * KP_];     // x split      [4096,3072]
__device__ __nv_bfloat16 g_ws[(size_t)3*C_ * KP_];   // W_attn split  [3072,3072]
__device__ __nv_bfloat16 g_ys[(size_t)M_ * KP_];     // y split       [4096,3072]
__device__ __nv_bfloat16 g_wps[(size_t)C_ * KP_];    // W_proj split  [1024,3072]

// ---------------------------------------------------------------------------
// fp32 -> bf16 hi/lo splits packed along K'=3K=3072.
// A-side: [hi, hi, lo];  B-side: [hi, lo, hi]  =>  hi*hi + hi*lo + lo*hi
// ---------------------------------------------------------------------------
__global__ void split_x_kernel(const float* __restrict__ src)
{
    int idx = blockIdx.x * blockDim.x + threadIdx.x;
    if (idx >= M_*C_/4) return;
    float4 v = ((const float4*)src)[idx];
    int r = idx >> 8;
    int k = (idx & 255) * 4;
    float vv[4] = {v.x, v.y, v.z, v.w};
    size_t base = (size_t)r * KP_ + k;
#pragma unroll
    for (int i = 0; i < 4; i++) {
        __nv_bfloat16 hi = __float2bfloat16(vv[i]);
        __nv_bfloat16 lo = __float2bfloat16(vv[i] - __bfloat162float(hi));
        g_xs[base + i]        = hi;
        g_xs[base + C_ + i]   = hi;
        g_xs[base + 2*C_ + i] = lo;
    }
}

__global__ void split_w_kernel(const float* __restrict__ src)
{
    int idx = blockIdx.x * blockDim.x + threadIdx.x;
    if (idx >= 3*C_*C_/4) return;
    float4 v = ((const float4*)src)[idx];
    int r = idx >> 8;
    int k = (idx & 255) * 4;
    float vv[4] = {v.x, v.y, v.z, v.w};
    size_t base = (size_t)r * KP_ + k;
#pragma unroll
    for (int i = 0; i < 4; i++) {
        __nv_bfloat16 hi = __float2bfloat16(vv[i]);
        __nv_bfloat16 lo = __float2bfloat16(vv[i] - __bfloat162float(hi));
        g_ws[base + i]        = hi;
        g_ws[base + C_ + i]   = lo;
        g_ws[base + 2*C_ + i] = hi;
    }
}

__global__ void split_wp_kernel(const float* __restrict__ src)
{
    int idx = blockIdx.x * blockDim.x + threadIdx.x;
    if (idx >= C_*C_/4) return;
    float4 v = ((const float4*)src)[idx];
    int r = idx >> 8;
    int k = (idx & 255) * 4;
    float vv[4] = {v.x, v.y, v.z, v.w};
    size_t base = (size_t)r * KP_ + k;
#pragma unroll
    for (int i = 0; i < 4; i++) {
        __nv_bfloat16 hi = __float2bfloat16(vv[i]);
        __nv_bfloat16 lo = __float2bfloat16(vv[i] - __bfloat162float(hi));
        g_wps[base + i]        = hi;
        g_wps[base + C_ + i]   = lo;
        g_wps[base + 2*C_ + i] = hi;
    }
}

// ---------------------------------------------------------------------------
// Tensor-core GEMM over pre-split operands (proven in R5).
// MODE 1: g_xs * g_ws^T + b_attn -> scatter q/k/v [B,H,T,D]
// MODE 0: g_ys * g_wps^T + b_proj -> out row-major [M,1024]
// ---------------------------------------------------------------------------
#define SSTRIDE 40

#define MMA16816(C4, A0,A1,A2,A3, B0,B1)                                      \
    asm volatile(                                                             \
        "mma.sync.aligned.m16n8k16.row.col.f32.bf16.bf16.f32 "                \
        "{%0,%1,%2,%3}, {%4,%5,%6,%7}, {%8,%9}, {%0,%1,%2,%3};\n"             \
        : "+f"((C4)[0]), "+f"((C4)[1]), "+f"((C4)[2]), "+f"((C4)[3])          \
        : "r"(A0), "r"(A1), "r"(A2), "r"(A3), "r"(B0), "r"(B1))

template<int MODE>
__global__ void __launch_bounds__(256) mma_gemm(
    const float* __restrict__ bias, float* __restrict__ out)
{
    const __nv_bfloat16* A  = (MODE == 1) ? g_xs : g_ys;
    const __nv_bfloat16* Bw = (MODE == 1) ? g_ws : g_wps;
    const int N = (MODE == 1) ? 3*C_ : C_;

    __shared__ __nv_bfloat16 As[2][128*SSTRIDE];
    __shared__ __nv_bfloat16 Bs[2][128*SSTRIDE];

    const int tid  = threadIdx.x;
    const int wid  = tid >> 5;
    const int lane = tid & 31;
    const int m0 = blockIdx.y * 128;
    const int n0 = blockIdx.x * 128;
    const int wm = (wid >> 1) * 32;
    const int wn = (wid & 1) * 64;
    const int lg = lane >> 2;
    const int lt = (lane & 3) * 2;

    const __nv_bfloat16* Ag = A  + (size_t)m0 * KP_;
    const __nv_bfloat16* Bg = Bw + (size_t)n0 * KP_;

    float c[2][8][4];
#pragma unroll
    for (int i = 0; i < 2; i++)
#pragma unroll
        for (int j = 0; j < 8; j++)
#pragma unroll
            for (int r = 0; r < 4; r++) c[i][j][r] = 0.f;

    uint4 ra[2], rb[2];
    const int nt = KP_ / 32;   // 96

#pragma unroll
    for (int i = 0; i < 2; i++) {
        int id = tid + 256*i, row = id >> 2, seg = id & 3;
        ra[i] = *(const uint4*)(Ag + (size_t)row*KP_ + seg*8);
        rb[i] = *(const uint4*)(Bg + (size_t)row*KP_ + seg*8);
    }
#pragma unroll
    for (int i = 0; i < 2; i++) {
        int id = tid + 256*i, row = id >> 2, seg = id & 3;
        *(uint4*)&As[0][row*SSTRIDE + seg*8] = ra[i];
        *(uint4*)&Bs[0][row*SSTRIDE + seg*8] = rb[i];
    }
    __syncthreads();

    for (int kt = 0; kt < nt; kt++) {
        const int buf = kt & 1;
        if (kt + 1 < nt) {
            const int k0 = (kt+1) * 32;
#pragma unroll
            for (int i = 0; i < 2; i++) {
                int id = tid + 256*i, row = id >> 2, seg = id & 3;
                ra[i] = *(const uint4*)(Ag + (size_t)row*KP_ + k0 + seg*8);
                rb[i] = *(const uint4*)(Bg + (size_t)row*KP_ + k0 + seg*8);
            }
        }

#pragma unroll
        for (int ks = 0; ks < 2; ks++) {
            const int k16 = ks * 16;
            unsigned int af[2][4];
#pragma unroll
            for (int mi = 0; mi < 2; mi++) {
                int r = wm + mi*16 + lg;
                int kc = k16 + lt;
                af[mi][0] = *(const unsigned int*)&As[buf][r*SSTRIDE + kc];
                af[mi][1] = *(const unsigned int*)&As[buf][(r+8)*SSTRIDE + kc];
                af[mi][2] = *(const unsigned int*)&As[buf][r*SSTRIDE + kc + 8];
                af[mi][3] = *(const unsigned int*)&As[buf][(r+8)*SSTRIDE + kc + 8];
            }
            unsigned int bfr[8][2];
#pragma unroll
            for (int nj = 0; nj < 8; nj++) {
                int r = wn + nj*8 + lg;
                int kc = k16 + lt;
                bfr[nj][0] = *(const unsigned int*)&Bs[buf][r*SSTRIDE + kc];
                bfr[nj][1] = *(const unsigned int*)&Bs[buf][r*SSTRIDE + kc + 8];
            }
#pragma unroll
            for (int mi = 0; mi < 2; mi++)
#pragma unroll
                for (int nj = 0; nj < 8; nj++)
                    MMA16816(c[mi][nj], af[mi][0], af[mi][1], af[mi][2], af[mi][3],
                             bfr[nj][0], bfr[nj][1]);
        }

        if (kt + 1 < nt) {
            const int nbuf = buf ^ 1;
#pragma unroll
            for (int i = 0; i < 2; i++) {
                int id = tid + 256*i, row = id >> 2, seg = id & 3;
                *(uint4*)&As[nbuf][row*SSTRIDE + seg*8] = ra[i];
                *(uint4*)&Bs[nbuf][row*SSTRIDE + seg*8] = rb[i];
            }
            __syncthreads();
        }
    }

#pragma unroll
    for (int mi = 0; mi < 2; mi++) {
#pragma unroll
        for (int nj = 0; nj < 8; nj++) {
            int row = m0 + wm + mi*16 + (lane >> 2);
            int col = n0 + wn + nj*8 + (lane & 3)*2;
            float b0 = bias[col], b1 = bias[col+1];
            float2 v0 = { c[mi][nj][0] + b0, c[mi][nj][1] + b1 };
            float2 v1 = { c[mi][nj][2] + b0, c[mi][nj][3] + b1 };
            if (MODE == 0) {
                *(float2*)&out[(size_t)row*N + col]     = v0;
                *(float2*)&out[(size_t)(row+8)*N + col] = v1;
            } else {
                int which = col >> 10;
                int h = (col & 1023) >> 6;
                int d = col & 63;
                float* dst = (which == 0) ? g_q : ((which == 1) ? g_k : g_v);
                int b = row >> 11, t = row & 2047;
                size_t base0 = ((size_t)(b*H_ + h)*T_ + t    )*D_ + d;
                size_t base1 = ((size_t)(b*H_ + h)*T_ + t + 8)*D_ + d;
                *(float2*)&dst[base0] = v0;
                *(float2*)&dst[base1] = v1;
            }
        }
    }
}

// ---------------------------------------------------------------------------
// RoPE in place on q,k (proven).
// ---------------------------------------------------------------------------
__global__ void rope_kernel()
{
    int idx = blockIdx.x * blockDim.x + threadIdx.x;
    int d  = idx & 31;
    int t  = (idx >> 5) & (T_ - 1);
    int bh = idx >> 16;
    size_t base = ((size_t)bh * T_ + t) * D_;

    const float L2_10000_OVER_32 = 13.287712379549449f / 32.0f;
    float f = exp2f(-(float)d * L2_10000_OVER_32);
    float ang = (float)t * f;
    float s, cc;
    sincosf(ang, &s, &cc);

    float q1 = g_q[base + d], q2 = g_q[base + d + 32];
    g_q[base + d]      = q1*cc - q2*s;
    g_q[base + d + 32] = q2*cc + q1*s;
    float k1 = g_k[base + d], k2 = g_k[base + d + 32];
    g_k[base + d]      = k1*cc - k2*s;
    g_k[base + d + 32] = k2*cc + k1*s;
}

// ---------------------------------------------------------------------------
// Tensor-core causal flash attention.
// Block: 256 threads (8 warps), Q tile 128 rows, K tile 64. Warp w owns
// q rows 16w..16w+15; each warp computes the FULL 64-col stripe (P stays
// register-resident). hi/lo split on both gemms with segment aliasing:
//   S:  ks0-3 qh*kh, ks4-7 qh*kl, ks8-11 ql*kh
//   PV: ks0-3 ph*vh, ks4-7 ph*vl, ks8-11 pl*vh
// Output written as split [hi|hi|lo] directly into g_ys for the proj gemm.
// ---------------------------------------------------------------------------
#define QST 136
#define KST 136
#define VST 72
#define SC_ 0.125f
#define ATTN_SMEM ((128*QST + 64*KST + 128*VST) * 2)

__global__ void __launch_bounds__(256) attn_mma()
{
    extern __shared__ __align__(16) __nv_bfloat16 smA[];
    __nv_bfloat16* Qs = smA;              // [128][QST]: cols [q_hi(64) | q_lo(64)]
    __nv_bfloat16* Ks = Qs + 128*QST;     // [64][KST]:  cols [k_hi | k_lo]
    __nv_bfloat16* Vs = Ks + 64*KST;      // [128][VST]: rows [v_hi(kpos 0..63) | v_lo]

    const int qt  = (int)gridDim.x - 1 - (int)blockIdx.x;   // heavy blocks first
    const int bh  = blockIdx.y;
    const int tid = threadIdx.x;
    const int wid = tid >> 5;
    const int lane = tid & 31;
    const int lg = lane >> 2;
    const int lq = lane & 3;

    // Q tile 128x64 -> split
    const float* qb = g_q + ((size_t)bh*T_ + qt*128)*D_;
#pragma unroll
    for (int i = 0; i < 8; i++) {
        int idx = tid + i*256;
        int r = idx >> 4, d4 = (idx & 15) << 2;
        float4 v = *(const float4*)(qb + r*64 + d4);
        float vv[4] = {v.x, v.y, v.z, v.w};
#pragma unroll
        for (int e = 0; e < 4; e += 2) {
            __nv_bfloat162 hp, lp;
            hp.x = __float2bfloat16(vv[e]);
            hp.y = __float2bfloat16(vv[e+1]);
            lp.x = __float2bfloat16(vv[e]   - __bfloat162float(hp.x));
            lp.y = __float2bfloat16(vv[e+1] - __bfloat162float(hp.y));
            *(__nv_bfloat162*)&Qs[r*QST + d4 + e]      = hp;
            *(__nv_bfloat162*)&Qs[r*QST + 64 + d4 + e] = lp;
        }
    }

    float m2[2] = {-CUDART_INF_F, -CUDART_INF_F};
    float l2[2] = {0.f, 0.f};
    float oc[8][4];
#pragma unroll
    for (int j = 0; j < 8; j++)
#pragma unroll
        for (int r = 0; r < 4; r++) oc[j][r] = 0.f;

    const int jmax = 2*qt + 1;
    for (int jt = 0; jt <= jmax; jt++) {
        __syncthreads();
        const float* kb = g_k + ((size_t)bh*T_ + jt*64)*D_;
        const float* vb = g_v + ((size_t)bh*T_ + jt*64)*D_;
#pragma unroll
        for (int i = 0; i < 4; i++) {
            int idx = tid + i*256;
            int r = idx >> 4, d4 = (idx & 15) << 2;
            float4 kv = *(const float4*)(kb + r*64 + d4);
            float4 vv = *(const float4*)(vb + r*64 + d4);
            float kk[4] = {kv.x, kv.y, kv.z, kv.w};
            float vf[4] = {vv.x, vv.y, vv.z, vv.w};
#pragma unroll
            for (int e = 0; e < 4; e += 2) {
                __nv_bfloat162 hp, lp;
                hp.x = __float2bfloat16(kk[e]);
                hp.y = __float2bfloat16(kk[e+1]);
                lp.x = __float2bfloat16(kk[e]   - __bfloat162float(hp.x));
                lp.y = __float2bfloat16(kk[e+1] - __bfloat162float(hp.y));
                *(__nv_bfloat162*)&Ks[r*KST + d4 + e]      = hp;
                *(__nv_bfloat162*)&Ks[r*KST + 64 + d4 + e] = lp;
                hp.x = __float2bfloat16(vf[e]);
                hp.y = __float2bfloat16(vf[e+1]);
                lp.x = __float2bfloat16(vf[e]   - __bfloat162float(hp.x));
                lp.y = __float2bfloat16(vf[e+1] - __bfloat162float(hp.y));
                *(__nv_bfloat162*)&Vs[r*VST + d4 + e]      = hp;
                *(__nv_bfloat162*)&Vs[(r+64)*VST + d4 + e] = lp;
            }
        }
        __syncthreads();

        // ---- S = Q K^T (16x64 per warp, k'=192 via aliased segments) ----
        float sc[8][4];
#pragma unroll
        for (int j = 0; j < 8; j++)
#pragma unroll
            for (int r = 0; r < 4; r++) sc[j][r] = 0.f;

#pragma unroll
        for (int ks = 0; ks < 12; ks++) {
            int kk4 = (ks & 3) * 16 + lq*2;
            int kcA = ((ks >= 8) ? 64 : 0) + kk4;              // Q: [hi,hi,lo]
            int kcB = ((ks >= 4 && ks < 8) ? 64 : 0) + kk4;    // K: [hi,lo,hi]
            int ra = wid*16 + lg;
            unsigned int a0 = *(const unsigned int*)&Qs[ra*QST + kcA];
            unsigned int a1 = *(const unsigned int*)&Qs[(ra+8)*QST + kcA];
            unsigned int a2 = *(const unsigned int*)&Qs[ra*QST + kcA + 8];
            unsigned int a3 = *(const unsigned int*)&Qs[(ra+8)*QST + kcA + 8];
#pragma unroll
            for (int nj = 0; nj < 8; nj++) {
                unsigned int b0 = *(const unsigned int*)&Ks[(nj*8+lg)*KST + kcB];
                unsigned int b1 = *(const unsigned int*)&Ks[(nj*8+lg)*KST + kcB + 8];
                MMA16816(sc[nj], a0, a1, a2, a3, b0, b1);
            }
        }

        // ---- mask + online softmax ----
        const bool needmask = (jt >= 2*qt);
        float rowm[2] = {-CUDART_INF_F, -CUDART_INF_F};
#pragma unroll
        for (int nj = 0; nj < 8; nj++) {
            if (needmask) {
                int kg  = jt*64 + nj*8 + lq*2;
                int qr0 = qt*128 + wid*16 + lg;
#pragma unroll
                for (int e = 0; e < 4; e++) {
                    if (kg + (e & 1) > qr0 + (e >> 1)*8) sc[nj][e] = -CUDART_INF_F;
                }
            }
            rowm[0] = fmaxf(rowm[0], fmaxf(sc[nj][0], sc[nj][1]));
            rowm[1] = fmaxf(rowm[1], fmaxf(sc[nj][2], sc[nj][3]));
        }
#pragma unroll
        for (int off = 1; off <= 2; off <<= 1) {
            rowm[0] = fmaxf(rowm[0], __shfl_xor_sync(0xffffffffu, rowm[0], off));
            rowm[1] = fmaxf(rowm[1], __shfl_xor_sync(0xffffffffu, rowm[1], off));
        }
        float corr[2];
#pragma unroll
        for (int h = 0; h < 2; h++) {
            float mn = fmaxf(m2[h], rowm[h]);
            corr[h] = __expf((m2[h] - mn) * SC_);
            m2[h] = mn;
        }
        float rs[2] = {0.f, 0.f};
        unsigned int ph[8][2], pl[8][2];
#pragma unroll
        for (int nj = 0; nj < 8; nj++) {
            float p0 = __expf((sc[nj][0] - m2[0]) * SC_);
            float p1 = __expf((sc[nj][1] - m2[0]) * SC_);
            float p2 = __expf((sc[nj][2] - m2[1]) * SC_);
            float p3 = __expf((sc[nj][3] - m2[1]) * SC_);
            rs[0] += p0 + p1;
            rs[1] += p2 + p3;
            __nv_bfloat162 h01, h23, l01, l23;
            h01.x = __float2bfloat16(p0); h01.y = __float2bfloat16(p1);
            l01.x = __float2bfloat16(p0 - __bfloat162float(h01.x));
            l01.y = __float2bfloat16(p1 - __bfloat162float(h01.y));
            h23.x = __float2bfloat16(p2); h23.y = __float2bfloat16(p3);
            l23.x = __float2bfloat16(p2 - __bfloat162float(h23.x));
            l23.y = __float2bfloat16(p3 - __bfloat162float(h23.y));
            ph[nj][0] = *(unsigned int*)&h01;
            ph[nj][1] = *(unsigned int*)&h23;
            pl[nj][0] = *(unsigned int*)&l01;
            pl[nj][1] = *(unsigned int*)&l23;
        }
#pragma unroll
        for (int off = 1; off <= 2; off <<= 1) {
            rs[0] += __shfl_xor_sync(0xffffffffu, rs[0], off);
            rs[1] += __shfl_xor_sync(0xffffffffu, rs[1], off);
        }
#pragma unroll
        for (int h = 0; h < 2; h++) l2[h] = l2[h]*corr[h] + rs[h];
#pragma unroll
        for (int nj = 0; nj < 8; nj++) {
            oc[nj][0] *= corr[0]; oc[nj][1] *= corr[0];
            oc[nj][2] *= corr[1]; oc[nj][3] *= corr[1];
        }

        // ---- O += P V ----
#pragma unroll
        for (int ks = 0; ks < 12; ks++) {
            int kk = ks & 3;
            unsigned int a0, a1, a2, a3;
            if (ks < 8) {
                a0 = ph[2*kk][0]; a1 = ph[2*kk][1];
                a2 = ph[2*kk+1][0]; a3 = ph[2*kk+1][1];
            } else {
                a0 = pl[2*kk][0]; a1 = pl[2*kk][1];
                a2 = pl[2*kk+1][0]; a3 = pl[2*kk+1][1];
            }
            int kcV = ((ks >= 4 && ks < 8) ? 64 : 0) + kk*16;   // V: [hi,lo,hi]
            int g = lane >> 3, rr = lane & 7;
#pragma unroll
            for (int njp = 0; njp < 4; njp++) {
                unsigned int addr = (unsigned int)__cvta_generic_to_shared(
                    &Vs[(kcV + rr + (g & 1)*8)*VST + njp*16 + (g >> 1)*8]);
                unsigned int b0, b1, b2, b3;
                asm volatile(
                    "ldmatrix.sync.aligned.m8n8.x4.trans.shared.b16 {%0,%1,%2,%3}, [%4];\n"
                    : "=r"(b0), "=r"(b1), "=r"(b2), "=r"(b3) : "r"(addr));
                MMA16816(oc[njp*2],   a0, a1, a2, a3, b0, b1);
                MMA16816(oc[njp*2+1], a0, a1, a2, a3, b2, b3);
            }
        }
    }

    // ---- epilogue: normalize, write split [hi|hi|lo] into g_ys ----
    int b = bh >> 4, h = bh & 15;
#pragma unroll
    for (int half = 0; half < 2; half++) {
        float inv = 1.0f / l2[half];
        int trow = qt*128 + wid*16 + lg + half*8;
        size_t rowbase = ((size_t)b*T_ + trow) * (size_t)KP_;
        int c0 = h*64 + lq*2;
#pragma unroll
        for (int nj = 0; nj < 8; nj++) {
            float y0 = oc[nj][half*2]   * inv;
            float y1 = oc[nj][half*2+1] * inv;
            __nv_bfloat162 hp, lp;
            hp.x = __float2bfloat16(y0);
            hp.y = __float2bfloat16(y1);
            lp.x = __float2bfloat16(y0 - __bfloat162float(hp.x));
            lp.y = __float2bfloat16(y1 - __bfloat162float(hp.y));
            int c = c0 + nj*8;
            *(__nv_bfloat162*)&g_ys[rowbase + c]        = hp;
            *(__nv_bfloat162*)&g_ys[rowbase + 1024 + c] = hp;
            *(__nv_bfloat162*)&g_ys[rowbase + 2048 + c] = lp;
        }
    }
}

// ---------------------------------------------------------------------------
extern "C" void kernel_launch(void* const* d_in, const int* in_sizes, int n_in,
                              void* d_out, int out_size)
{
    const float* x      = (const float*)d_in[0];
    const float* W_attn = (const float*)d_in[1];
    const float* b_attn = (const float*)d_in[2];
    const float* W_proj = (const float*)d_in[3];
    const float* b_proj = (const float*)d_in[4];
    float* out = (float*)d_out;

    split_x_kernel<<<(M_*C_/4 + 255)/256, 256>>>(x);
    split_w_kernel<<<(3*C_*C_/4 + 255)/256, 256>>>(W_attn);
    split_wp_kernel<<<(C_*C_/4 + 255)/256, 256>>>(W_proj);

    mma_gemm<1><<<dim3(3*C_/128, M_/128), 256>>>(b_attn, nullptr);

    rope_kernel<<<(B_*H_*T_*32)/256, 256>>>();

    cudaFuncSetAttribute(attn_mma, cudaFuncAttributeMaxDynamicSharedMemorySize, ATTN_SMEM);
    attn_mma<<<dim3(T_/128, B_*H_), 256, ATTN_SMEM>>>();

    mma_gemm<0><<<dim3(C_/128, M_/128), 256>>>(b_proj, out);
}

// round 7
// speedup vs baseline: 1.9170x; 1.1327x over previous
#include <cuda_runtime.h>
#include <cuda_bf16.h>
#include <math_constants.h>
#include <cstdint>

// Problem constants
#define B_  2
#define T_  2048
#define C_  1024
#define H_  16
#define D_  64
#define M_  (B_*T_)          // 4096 rows
#define BHTD (B_*H_*T_*D_)
#define KP_ (3*C_)           // 3072 split-K

// Scratch (device globals, referenced directly from kernels)
__device__ float g_q[BHTD];
__device__ float g_k[BHTD];
__device__ float g_v[BHTD];
__device__ __nv_bfloat16 g_xs[(size_t)M_ * KP_];     // x split      [4096,3072]
__device__ __nv_bfloat16 g_ws[(size_t)3*C_ * KP_];   // W_attn split  [3072,3072]
__device__ __nv_bfloat16 g_ys[(size_t)M_ * KP_];     // y split       [4096,3072]
__device__ __nv_bfloat16 g_wps[(size_t)C_ * KP_];    // W_proj split  [1024,3072]

// ---------------------------------------------------------------------------
// fp32 -> bf16 hi/lo splits packed along K'=3K=3072.
// A-side: [hi, hi, lo];  B-side: [hi, lo, hi]  =>  hi*hi + hi*lo + lo*hi
// ---------------------------------------------------------------------------
__global__ void split_x_kernel(const float* __restrict__ src)
{
    int idx = blockIdx.x * blockDim.x + threadIdx.x;
    if (idx >= M_*C_/4) return;
    float4 v = ((const float4*)src)[idx];
    int r = idx >> 8;
    int k = (idx & 255) * 4;
    float vv[4] = {v.x, v.y, v.z, v.w};
    size_t base = (size_t)r * KP_ + k;
#pragma unroll
    for (int i = 0; i < 4; i++) {
        __nv_bfloat16 hi = __float2bfloat16(vv[i]);
        __nv_bfloat16 lo = __float2bfloat16(vv[i] - __bfloat162float(hi));
        g_xs[base + i]        = hi;
        g_xs[base + C_ + i]   = hi;
        g_xs[base + 2*C_ + i] = lo;
    }
}

__global__ void split_w_kernel(const float* __restrict__ src)
{
    int idx = blockIdx.x * blockDim.x + threadIdx.x;
    if (idx >= 3*C_*C_/4) return;
    float4 v = ((const float4*)src)[idx];
    int r = idx >> 8;
    int k = (idx & 255) * 4;
    float vv[4] = {v.x, v.y, v.z, v.w};
    size_t base = (size_t)r * KP_ + k;
#pragma unroll
    for (int i = 0; i < 4; i++) {
        __nv_bfloat16 hi = __float2bfloat16(vv[i]);
        __nv_bfloat16 lo = __float2bfloat16(vv[i] - __bfloat162float(hi));
        g_ws[base + i]        = hi;
        g_ws[base + C_ + i]   = lo;
        g_ws[base + 2*C_ + i] = hi;
    }
}

__global__ void split_wp_kernel(const float* __restrict__ src)
{
    int idx = blockIdx.x * blockDim.x + threadIdx.x;
    if (idx >= C_*C_/4) return;
    float4 v = ((const float4*)src)[idx];
    int r = idx >> 8;
    int k = (idx & 255) * 4;
    float vv[4] = {v.x, v.y, v.z, v.w};
    size_t base = (size_t)r * KP_ + k;
#pragma unroll
    for (int i = 0; i < 4; i++) {
        __nv_bfloat16 hi = __float2bfloat16(vv[i]);
        __nv_bfloat16 lo = __float2bfloat16(vv[i] - __bfloat162float(hi));
        g_wps[base + i]        = hi;
        g_wps[base + C_ + i]   = lo;
        g_wps[base + 2*C_ + i] = hi;
    }
}

// ---------------------------------------------------------------------------
// Tensor-core GEMM over pre-split operands.
// 256x128 tile, 512 threads (16 warps: 8 M-groups x 2 N-groups, warp 32x64),
// 3-stage cp.async pipeline, explicit-LDS fragments (proven layout).
// MODE 1: g_xs * g_ws^T + b_attn -> scatter q/k/v [B,H,T,D]
// MODE 0: g_ys * g_wps^T + b_proj -> out row-major [M,1024]
// ---------------------------------------------------------------------------
#define SSTRIDE 40
#define GSTAGES 3
#define GEMM_SMEM ((GSTAGES*(256+128)*SSTRIDE)*2)

#define MMA16816(C4, A0,A1,A2,A3, B0,B1)                                      \
    asm volatile(                                                             \
        "mma.sync.aligned.m16n8k16.row.col.f32.bf16.bf16.f32 "                \
        "{%0,%1,%2,%3}, {%4,%5,%6,%7}, {%8,%9}, {%0,%1,%2,%3};\n"             \
        : "+f"((C4)[0]), "+f"((C4)[1]), "+f"((C4)[2]), "+f"((C4)[3])          \
        : "r"(A0), "r"(A1), "r"(A2), "r"(A3), "r"(B0), "r"(B1))

#define CP_ASYNC16(smem_u32, gptr)                                            \
    asm volatile("cp.async.cg.shared.global [%0], [%1], 16;\n"                \
                 :: "r"(smem_u32), "l"(gptr))

template<int MODE>
__global__ void __launch_bounds__(512) mma_gemm(
    const float* __restrict__ bias, float* __restrict__ out)
{
    const __nv_bfloat16* A  = (MODE == 1) ? g_xs : g_ys;
    const __nv_bfloat16* Bw = (MODE == 1) ? g_ws : g_wps;
    const int N = (MODE == 1) ? 3*C_ : C_;

    extern __shared__ __align__(16) __nv_bfloat16 gsm[];
    __nv_bfloat16* As = gsm;                          // [GSTAGES][256*SSTRIDE]
    __nv_bfloat16* Bs = gsm + GSTAGES*256*SSTRIDE;    // [GSTAGES][128*SSTRIDE]

    const int tid  = threadIdx.x;
    const int wid  = tid >> 5;
    const int lane = tid & 31;
    const int m0 = blockIdx.y * 256;
    const int n0 = blockIdx.x * 128;
    const int wm = (wid >> 1) * 32;
    const int wn = (wid & 1) * 64;
    const int lg = lane >> 2;
    const int lt = (lane & 3) * 2;

    const __nv_bfloat16* Ag = A  + (size_t)m0 * KP_;
    const __nv_bfloat16* Bg = Bw + (size_t)n0 * KP_;

    // per-thread load slots
    const int arow0 = tid >> 1;                 // i=0: rows 0..255 (tid+512*0)>>1? no:
    // A: idx = tid + 512*i, row = idx>>2, seg = idx&3  (2 slots per thread)
    // B: row = tid>>2, seg = tid&3                     (1 slot per thread)
    const int brow = tid >> 2, bseg = tid & 3;

    float c[2][8][4];
#pragma unroll
    for (int i = 0; i < 2; i++)
#pragma unroll
        for (int j = 0; j < 8; j++)
#pragma unroll
            for (int r = 0; r < 4; r++) c[i][j][r] = 0.f;

    const int nt = KP_ / 32;   // 96

    // pipeline issue helper (macro to keep addresses simple)
#define ISSUE_STAGE(stage, k0)                                                \
    do {                                                                      \
        __nv_bfloat16* asb = As + (stage)*256*SSTRIDE;                        \
        __nv_bfloat16* bsb = Bs + (stage)*128*SSTRIDE;                        \
        _Pragma("unroll")                                                     \
        for (int i = 0; i < 2; i++) {                                         \
            int idx = tid + 512*i, row = idx >> 2, seg = idx & 3;             \
            unsigned int sa = (unsigned int)__cvta_generic_to_shared(         \
                &asb[row*SSTRIDE + seg*8]);                                   \
            CP_ASYNC16(sa, Ag + (size_t)row*KP_ + (k0) + seg*8);              \
        }                                                                     \
        {                                                                     \
            unsigned int sb = (unsigned int)__cvta_generic_to_shared(         \
                &bsb[brow*SSTRIDE + bseg*8]);                                 \
            CP_ASYNC16(sb, Bg + (size_t)brow*KP_ + (k0) + bseg*8);            \
        }                                                                     \
        asm volatile("cp.async.commit_group;\n");                             \
    } while (0)

    ISSUE_STAGE(0, 0);
    ISSUE_STAGE(1, 32);

    for (int kt = 0; kt < nt; kt++) {
        const int stage = kt % GSTAGES;
        asm volatile("cp.async.wait_group %0;\n" :: "n"(1));
        __syncthreads();

        if (kt + 2 < nt) {
            ISSUE_STAGE((kt + 2) % GSTAGES, (kt + 2) * 32);
        }

        const __nv_bfloat16* asb = As + stage*256*SSTRIDE;
        const __nv_bfloat16* bsb = Bs + stage*128*SSTRIDE;

#pragma unroll
        for (int ks = 0; ks < 2; ks++) {
            const int k16 = ks * 16;
            unsigned int af[2][4];
#pragma unroll
            for (int mi = 0; mi < 2; mi++) {
                int r = wm + mi*16 + lg;
                int kc = k16 + lt;
                af[mi][0] = *(const unsigned int*)&asb[r*SSTRIDE + kc];
                af[mi][1] = *(const unsigned int*)&asb[(r+8)*SSTRIDE + kc];
                af[mi][2] = *(const unsigned int*)&asb[r*SSTRIDE + kc + 8];
                af[mi][3] = *(const unsigned int*)&asb[(r+8)*SSTRIDE + kc + 8];
            }
            unsigned int bfr[8][2];
#pragma unroll
            for (int nj = 0; nj < 8; nj++) {
                int r = wn + nj*8 + lg;
                int kc = k16 + lt;
                bfr[nj][0] = *(const unsigned int*)&bsb[r*SSTRIDE + kc];
                bfr[nj][1] = *(const unsigned int*)&bsb[r*SSTRIDE + kc + 8];
            }
#pragma unroll
            for (int mi = 0; mi < 2; mi++)
#pragma unroll
                for (int nj = 0; nj < 8; nj++)
                    MMA16816(c[mi][nj], af[mi][0], af[mi][1], af[mi][2], af[mi][3],
                             bfr[nj][0], bfr[nj][1]);
        }
        __syncthreads();   // all reads of this stage done before it is refilled
    }
#undef ISSUE_STAGE

#pragma unroll
    for (int mi = 0; mi < 2; mi++) {
#pragma unroll
        for (int nj = 0; nj < 8; nj++) {
            int row = m0 + wm + mi*16 + (lane >> 2);
            int col = n0 + wn + nj*8 + (lane & 3)*2;
            float b0 = bias[col], b1 = bias[col+1];
            float2 v0 = { c[mi][nj][0] + b0, c[mi][nj][1] + b1 };
            float2 v1 = { c[mi][nj][2] + b0, c[mi][nj][3] + b1 };
            if (MODE == 0) {
                *(float2*)&out[(size_t)row*N + col]     = v0;
                *(float2*)&out[(size_t)(row+8)*N + col] = v1;
            } else {
                int which = col >> 10;
                int h = (col & 1023) >> 6;
                int d = col & 63;
                float* dst = (which == 0) ? g_q : ((which == 1) ? g_k : g_v);
                int b = row >> 11, t = row & 2047;
                size_t base0 = ((size_t)(b*H_ + h)*T_ + t    )*D_ + d;
                size_t base1 = ((size_t)(b*H_ + h)*T_ + t + 8)*D_ + d;
                *(float2*)&dst[base0] = v0;
                *(float2*)&dst[base1] = v1;
            }
        }
    }
}

// ---------------------------------------------------------------------------
// RoPE in place on q,k (proven).
// ---------------------------------------------------------------------------
__global__ void rope_kernel()
{
    int idx = blockIdx.x * blockDim.x + threadIdx.x;
    int d  = idx & 31;
    int t  = (idx >> 5) & (T_ - 1);
    int bh = idx >> 16;
    size_t base = ((size_t)bh * T_ + t) * D_;

    const float L2_10000_OVER_32 = 13.287712379549449f / 32.0f;
    float f = exp2f(-(float)d * L2_10000_OVER_32);
    float ang = (float)t * f;
    float s, cc;
    sincosf(ang, &s, &cc);

    float q1 = g_q[base + d], q2 = g_q[base + d + 32];
    g_q[base + d]      = q1*cc - q2*s;
    g_q[base + d + 32] = q2*cc + q1*s;
    float k1 = g_k[base + d], k2 = g_k[base + d + 32];
    g_k[base + d]      = k1*cc - k2*s;
    g_k[base + d + 32] = k2*cc + k1*s;
}

// ---------------------------------------------------------------------------
// Tensor-core causal flash attention (proven in R6, unchanged).
// ---------------------------------------------------------------------------
#define QST 136
#define KST 136
#define VST 72
#define SC_ 0.125f
#define ATTN_SMEM ((128*QST + 64*KST + 128*VST) * 2)

__global__ void __launch_bounds__(256) attn_mma()
{
    extern __shared__ __align__(16) __nv_bfloat16 smA[];
    __nv_bfloat16* Qs = smA;              // [128][QST]: cols [q_hi(64) | q_lo(64)]
    __nv_bfloat16* Ks = Qs + 128*QST;     // [64][KST]:  cols [k_hi | k_lo]
    __nv_bfloat16* Vs = Ks + 64*KST;      // [128][VST]: rows [v_hi | v_lo]

    const int qt  = (int)gridDim.x - 1 - (int)blockIdx.x;   // heavy blocks first
    const int bh  = blockIdx.y;
    const int tid = threadIdx.x;
    const int wid = tid >> 5;
    const int lane = tid & 31;
    const int lg = lane >> 2;
    const int lq = lane & 3;

    const float* qb = g_q + ((size_t)bh*T_ + qt*128)*D_;
#pragma unroll
    for (int i = 0; i < 8; i++) {
        int idx = tid + i*256;
        int r = idx >> 4, d4 = (idx & 15) << 2;
        float4 v = *(const float4*)(qb + r*64 + d4);
        float vv[4] = {v.x, v.y, v.z, v.w};
#pragma unroll
        for (int e = 0; e < 4; e += 2) {
            __nv_bfloat162 hp, lp;
            hp.x = __float2bfloat16(vv[e]);
            hp.y = __float2bfloat16(vv[e+1]);
            lp.x = __float2bfloat16(vv[e]   - __bfloat162float(hp.x));
            lp.y = __float2bfloat16(vv[e+1] - __bfloat162float(hp.y));
            *(__nv_bfloat162*)&Qs[r*QST + d4 + e]      = hp;
            *(__nv_bfloat162*)&Qs[r*QST + 64 + d4 + e] = lp;
        }
    }

    float m2[2] = {-CUDART_INF_F, -CUDART_INF_F};
    float l2[2] = {0.f, 0.f};
    float oc[8][4];
#pragma unroll
    for (int j = 0; j < 8; j++)
#pragma unroll
        for (int r = 0; r < 4; r++) oc[j][r] = 0.f;

    const int jmax = 2*qt + 1;
    for (int jt = 0; jt <= jmax; jt++) {
        __syncthreads();
        const float* kb = g_k + ((size_t)bh*T_ + jt*64)*D_;
        const float* vb = g_v + ((size_t)bh*T_ + jt*64)*D_;
#pragma unroll
        for (int i = 0; i < 4; i++) {
            int idx = tid + i*256;
            int r = idx >> 4, d4 = (idx & 15) << 2;
            float4 kv = *(const float4*)(kb + r*64 + d4);
            float4 vv = *(const float4*)(vb + r*64 + d4);
            float kk[4] = {kv.x, kv.y, kv.z, kv.w};
            float vf[4] = {vv.x, vv.y, vv.z, vv.w};
#pragma unroll
            for (int e = 0; e < 4; e += 2) {
                __nv_bfloat162 hp, lp;
                hp.x = __float2bfloat16(kk[e]);
                hp.y = __float2bfloat16(kk[e+1]);
                lp.x = __float2bfloat16(kk[e]   - __bfloat162float(hp.x));
                lp.y = __float2bfloat16(kk[e+1] - __bfloat162float(hp.y));
                *(__nv_bfloat162*)&Ks[r*KST + d4 + e]      = hp;
                *(__nv_bfloat162*)&Ks[r*KST + 64 + d4 + e] = lp;
                hp.x = __float2bfloat16(vf[e]);
                hp.y = __float2bfloat16(vf[e+1]);
                lp.x = __float2bfloat16(vf[e]   - __bfloat162float(hp.x));
                lp.y = __float2bfloat16(vf[e+1] - __bfloat162float(hp.y));
                *(__nv_bfloat162*)&Vs[r*VST + d4 + e]      = hp;
                *(__nv_bfloat162*)&Vs[(r+64)*VST + d4 + e] = lp;
            }
        }
        __syncthreads();

        float sc[8][4];
#pragma unroll
        for (int j = 0; j < 8; j++)
#pragma unroll
            for (int r = 0; r < 4; r++) sc[j][r] = 0.f;

#pragma unroll
        for (int ks = 0; ks < 12; ks++) {
            int kk4 = (ks & 3) * 16 + lq*2;
            int kcA = ((ks >= 8) ? 64 : 0) + kk4;
            int kcB = ((ks >= 4 && ks < 8) ? 64 : 0) + kk4;
            int ra = wid*16 + lg;
            unsigned int a0 = *(const unsigned int*)&Qs[ra*QST + kcA];
            unsigned int a1 = *(const unsigned int*)&Qs[(ra+8)*QST + kcA];
            unsigned int a2 = *(const unsigned int*)&Qs[ra*QST + kcA + 8];
            unsigned int a3 = *(const unsigned int*)&Qs[(ra+8)*QST + kcA + 8];
#pragma unroll
            for (int nj = 0; nj < 8; nj++) {
                unsigned int b0 = *(const unsigned int*)&Ks[(nj*8+lg)*KST + kcB];
                unsigned int b1 = *(const unsigned int*)&Ks[(nj*8+lg)*KST + kcB + 8];
                MMA16816(sc[nj], a0, a1, a2, a3, b0, b1);
            }
        }

        const bool needmask = (jt >= 2*qt);
        float rowm[2] = {-CUDART_INF_F, -CUDART_INF_F};
#pragma unroll
        for (int nj = 0; nj < 8; nj++) {
            if (needmask) {
                int kg  = jt*64 + nj*8 + lq*2;
                int qr0 = qt*128 + wid*16 + lg;
#pragma unroll
                for (int e = 0; e < 4; e++) {
                    if (kg + (e & 1) > qr0 + (e >> 1)*8) sc[nj][e] = -CUDART_INF_F;
                }
            }
            rowm[0] = fmaxf(rowm[0], fmaxf(sc[nj][0], sc[nj][1]));
            rowm[1] = fmaxf(rowm[1], fmaxf(sc[nj][2], sc[nj][3]));
        }
#pragma unroll
        for (int off = 1; off <= 2; off <<= 1) {
            rowm[0] = fmaxf(rowm[0], __shfl_xor_sync(0xffffffffu, rowm[0], off));
            rowm[1] = fmaxf(rowm[1], __shfl_xor_sync(0xffffffffu, rowm[1], off));
        }
        float corr[2];
#pragma unroll
        for (int h = 0; h < 2; h++) {
            float mn = fmaxf(m2[h], rowm[h]);
            corr[h] = __expf((m2[h] - mn) * SC_);
            m2[h] = mn;
        }
        float rs[2] = {0.f, 0.f};
        unsigned int ph[8][2], pl[8][2];
#pragma unroll
        for (int nj = 0; nj < 8; nj++) {
            float p0 = __expf((sc[nj][0] - m2[0]) * SC_);
            float p1 = __expf((sc[nj][1] - m2[0]) * SC_);
            float p2 = __expf((sc[nj][2] - m2[1]) * SC_);
            float p3 = __expf((sc[nj][3] - m2[1]) * SC_);
            rs[0] += p0 + p1;
            rs[1] += p2 + p3;
            __nv_bfloat162 h01, h23, l01, l23;
            h01.x = __float2bfloat16(p0); h01.y = __float2bfloat16(p1);
            l01.x = __float2bfloat16(p0 - __bfloat162float(h01.x));
            l01.y = __float2bfloat16(p1 - __bfloat162float(h01.y));
            h23.x = __float2bfloat16(p2); h23.y = __float2bfloat16(p3);
            l23.x = __float2bfloat16(p2 - __bfloat162float(h23.x));
            l23.y = __float2bfloat16(p3 - __bfloat162float(h23.y));
            ph[nj][0] = *(unsigned int*)&h01;
            ph[nj][1] = *(unsigned int*)&h23;
            pl[nj][0] = *(unsigned int*)&l01;
            pl[nj][1] = *(unsigned int*)&l23;
        }
#pragma unroll
        for (int off = 1; off <= 2; off <<= 1) {
            rs[0] += __shfl_xor_sync(0xffffffffu, rs[0], off);
            rs[1] += __shfl_xor_sync(0xffffffffu, rs[1], off);
        }
#pragma unroll
        for (int h = 0; h < 2; h++) l2[h] = l2[h]*corr[h] + rs[h];
#pragma unroll
        for (int nj = 0; nj < 8; nj++) {
            oc[nj][0] *= corr[0]; oc[nj][1] *= corr[0];
            oc[nj][2] *= corr[1]; oc[nj][3] *= corr[1];
        }

#pragma unroll
        for (int ks = 0; ks < 12; ks++) {
            int kk = ks & 3;
            unsigned int a0, a1, a2, a3;
            if (ks < 8) {
                a0 = ph[2*kk][0]; a1 = ph[2*kk][1];
                a2 = ph[2*kk+1][0]; a3 = ph[2*kk+1][1];
            } else {
                a0 = pl[2*kk][0]; a1 = pl[2*kk][1];
                a2 = pl[2*kk+1][0]; a3 = pl[2*kk+1][1];
            }
            int kcV = ((ks >= 4 && ks < 8) ? 64 : 0) + kk*16;
            int g = lane >> 3, rr = lane & 7;
#pragma unroll
            for (int njp = 0; njp < 4; njp++) {
                unsigned int addr = (unsigned int)__cvta_generic_to_shared(
                    &Vs[(kcV + rr + (g & 1)*8)*VST + njp*16 + (g >> 1)*8]);
                unsigned int b0, b1, b2, b3;
                asm volatile(
                    "ldmatrix.sync.aligned.m8n8.x4.trans.shared.b16 {%0,%1,%2,%3}, [%4];\n"
                    : "=r"(b0), "=r"(b1), "=r"(b2), "=r"(b3) : "r"(addr));
                MMA16816(oc[njp*2],   a0, a1, a2, a3, b0, b1);
                MMA16816(oc[njp*2+1], a0, a1, a2, a3, b2, b3);
            }
        }
    }

    int b = bh >> 4, h = bh & 15;
#pragma unroll
    for (int half = 0; half < 2; half++) {
        float inv = 1.0f / l2[half];
        int trow = qt*128 + wid*16 + lg + half*8;
        size_t rowbase = ((size_t)b*T_ + trow) * (size_t)KP_;
        int c0 = h*64 + lq*2;
#pragma unroll
        for (int nj = 0; nj < 8; nj++) {
            float y0 = oc[nj][half*2]   * inv;
            float y1 = oc[nj][half*2+1] * inv;
            __nv_bfloat162 hp, lp;
            hp.x = __float2bfloat16(y0);
            hp.y = __float2bfloat16(y1);
            lp.x = __float2bfloat16(y0 - __bfloat162float(hp.x));
            lp.y = __float2bfloat16(y1 - __bfloat162float(hp.y));
            int c = c0 + nj*8;
            *(__nv_bfloat162*)&g_ys[rowbase + c]        = hp;
            *(__nv_bfloat162*)&g_ys[rowbase + 1024 + c] = hp;
            *(__nv_bfloat162*)&g_ys[rowbase + 2048 + c] = lp;
        }
    }
}

// ---------------------------------------------------------------------------
extern "C" void kernel_launch(void* const* d_in, const int* in_sizes, int n_in,
                              void* d_out, int out_size)
{
    const float* x      = (const float*)d_in[0];
    const float* W_attn = (const float*)d_in[1];
    const float* b_attn = (const float*)d_in[2];
    const float* W_proj = (const float*)d_in[3];
    const float* b_proj = (const float*)d_in[4];
    float* out = (float*)d_out;

    split_x_kernel<<<(M_*C_/4 + 255)/256, 256>>>(x);
    split_w_kernel<<<(3*C_*C_/4 + 255)/256, 256>>>(W_attn);
    split_wp_kernel<<<(C_*C_/4 + 255)/256, 256>>>(W_proj);

    cudaFuncSetAttribute(mma_gemm<1>, cudaFuncAttributeMaxDynamicSharedMemorySize, GEMM_SMEM);
    cudaFuncSetAttribute(mma_gemm<0>, cudaFuncAttributeMaxDynamicSharedMemorySize, GEMM_SMEM);

    mma_gemm<1><<<dim3(3*C_/128, M_/256), 512, GEMM_SMEM>>>(b_attn, nullptr);

    rope_kernel<<<(B_*H_*T_*32)/256, 256>>>();

    cudaFuncSetAttribute(attn_mma, cudaFuncAttributeMaxDynamicSharedMemorySize, ATTN_SMEM);
    attn_mma<<<dim3(T_/128, B_*H_), 256, ATTN_SMEM>>>();

    mma_gemm<0><<<dim3(C_/128, M_/256), 512, GEMM_SMEM>>>(b_proj, out);
}

// round 8
// speedup vs baseline: 2.0033x; 1.0450x over previous
#include <cuda_runtime.h>
#include <cuda_bf16.h>
#include <math_constants.h>
#include <cstdint>

// Problem constants
#define B_  2
#define T_  2048
#define C_  1024
#define H_  16
#define D_  64
#define M_  (B_*T_)          // 4096 rows
#define BHTD (B_*H_*T_*D_)
#define KP_ (3*C_)           // 3072 split-K

// Scratch (device globals, referenced directly from kernels)
__device__ float g_q[BHTD];
__device__ float g_k[BHTD];
__device__ float g_v[BHTD];
__device__ __nv_bfloat16 g_xs[(size_t)M_ * KP_];     // x split      [4096,3072]
__device__ __nv_bfloat16 g_ws[(size_t)3*C_ * KP_];   // W_attn split  [3072,3072]
__device__ __nv_bfloat16 g_ys[(size_t)M_ * KP_];     // y split       [4096,3072]
__device__ __nv_bfloat16 g_wps[(size_t)C_ * KP_];    // W_proj split  [1024,3072]

// ---------------------------------------------------------------------------
// fp32 -> bf16 hi/lo splits packed along K'=3K=3072.
// A-side: [hi, hi, lo];  B-side: [hi, lo, hi]  =>  hi*hi + hi*lo + lo*hi
// ---------------------------------------------------------------------------
__global__ void split_x_kernel(const float* __restrict__ src)
{
    int idx = blockIdx.x * blockDim.x + threadIdx.x;
    if (idx >= M_*C_/4) return;
    float4 v = ((const float4*)src)[idx];
    int r = idx >> 8;
    int k = (idx & 255) * 4;
    float vv[4] = {v.x, v.y, v.z, v.w};
    size_t base = (size_t)r * KP_ + k;
#pragma unroll
    for (int i = 0; i < 4; i++) {
        __nv_bfloat16 hi = __float2bfloat16(vv[i]);
        __nv_bfloat16 lo = __float2bfloat16(vv[i] - __bfloat162float(hi));
        g_xs[base + i]        = hi;
        g_xs[base + C_ + i]   = hi;
        g_xs[base + 2*C_ + i] = lo;
    }
}

__global__ void split_w_kernel(const float* __restrict__ src)
{
    int idx = blockIdx.x * blockDim.x + threadIdx.x;
    if (idx >= 3*C_*C_/4) return;
    float4 v = ((const float4*)src)[idx];
    int r = idx >> 8;
    int k = (idx & 255) * 4;
    float vv[4] = {v.x, v.y, v.z, v.w};
    size_t base = (size_t)r * KP_ + k;
#pragma unroll
    for (int i = 0; i < 4; i++) {
        __nv_bfloat16 hi = __float2bfloat16(vv[i]);
        __nv_bfloat16 lo = __float2bfloat16(vv[i] - __bfloat162float(hi));
        g_ws[base + i]        = hi;
        g_ws[base + C_ + i]   = lo;
        g_ws[base + 2*C_ + i] = hi;
    }
}

__global__ void split_wp_kernel(const float* __restrict__ src)
{
    int idx = blockIdx.x * blockDim.x + threadIdx.x;
    if (idx >= C_*C_/4) return;
    float4 v = ((const float4*)src)[idx];
    int r = idx >> 8;
    int k = (idx & 255) * 4;
    float vv[4] = {v.x, v.y, v.z, v.w};
    size_t base = (size_t)r * KP_ + k;
#pragma unroll
    for (int i = 0; i < 4; i++) {
        __nv_bfloat16 hi = __float2bfloat16(vv[i]);
        __nv_bfloat16 lo = __float2bfloat16(vv[i] - __bfloat162float(hi));
        g_wps[base + i]        = hi;
        g_wps[base + C_ + i]   = lo;
        g_wps[base + 2*C_ + i] = hi;
    }
}

// ---------------------------------------------------------------------------
// Tensor-core GEMM over pre-split operands.
// 256x128 tile, 512 threads (16 warps: 8 M-groups x 2 N-groups, warp 32x64),
// 3-stage cp.async pipeline, ldmatrix.x4 fragment loads.
// MODE 1: g_xs * g_ws^T + b_attn -> scatter q/k/v [B,H,T,D]
// MODE 0: g_ys * g_wps^T + b_proj -> out row-major [M,1024]
// ---------------------------------------------------------------------------
#define SSTRIDE 40
#define GSTAGES 3
#define GEMM_SMEM ((GSTAGES*(256+128)*SSTRIDE)*2)

#define MMA16816(C4, A0,A1,A2,A3, B0,B1)                                      \
    asm volatile(                                                             \
        "mma.sync.aligned.m16n8k16.row.col.f32.bf16.bf16.f32 "                \
        "{%0,%1,%2,%3}, {%4,%5,%6,%7}, {%8,%9}, {%0,%1,%2,%3};\n"             \
        : "+f"((C4)[0]), "+f"((C4)[1]), "+f"((C4)[2]), "+f"((C4)[3])          \
        : "r"(A0), "r"(A1), "r"(A2), "r"(A3), "r"(B0), "r"(B1))

#define LDSM_X4(R0,R1,R2,R3, ptr)                                             \
    do {                                                                      \
        unsigned int _a = (unsigned int)__cvta_generic_to_shared(ptr);        \
        asm volatile(                                                         \
            "ldmatrix.sync.aligned.m8n8.x4.shared.b16 {%0,%1,%2,%3}, [%4];\n" \
            : "=r"(R0), "=r"(R1), "=r"(R2), "=r"(R3) : "r"(_a));              \
    } while (0)

#define CP_ASYNC16(smem_u32, gptr)                                            \
    asm volatile("cp.async.cg.shared.global [%0], [%1], 16;\n"                \
                 :: "r"(smem_u32), "l"(gptr))

template<int MODE>
__global__ void __launch_bounds__(512) mma_gemm(
    const float* __restrict__ bias, float* __restrict__ out)
{
    const __nv_bfloat16* A  = (MODE == 1) ? g_xs : g_ys;
    const __nv_bfloat16* Bw = (MODE == 1) ? g_ws : g_wps;
    const int N = (MODE == 1) ? 3*C_ : C_;

    extern __shared__ __align__(16) __nv_bfloat16 gsm[];
    __nv_bfloat16* As = gsm;                          // [GSTAGES][256*SSTRIDE]
    __nv_bfloat16* Bs = gsm + GSTAGES*256*SSTRIDE;    // [GSTAGES][128*SSTRIDE]

    const int tid  = threadIdx.x;
    const int wid  = tid >> 5;
    const int lane = tid & 31;
    const int m0 = blockIdx.y * 256;
    const int n0 = blockIdx.x * 128;
    const int wm = (wid >> 1) * 32;
    const int wn = (wid & 1) * 64;
    // ldmatrix addressing: lane -> (row = lane&15, col-half = lane>>4)
    const int lrow = lane & 15;
    const int lcol = (lane >> 4) << 3;

    const __nv_bfloat16* Ag = A  + (size_t)m0 * KP_;
    const __nv_bfloat16* Bg = Bw + (size_t)n0 * KP_;

    const int brow = tid >> 2, bseg = tid & 3;

    float c[2][8][4];
#pragma unroll
    for (int i = 0; i < 2; i++)
#pragma unroll
        for (int j = 0; j < 8; j++)
#pragma unroll
            for (int r = 0; r < 4; r++) c[i][j][r] = 0.f;

    const int nt = KP_ / 32;   // 96

#define ISSUE_STAGE(stage, k0)                                                \
    do {                                                                      \
        __nv_bfloat16* asb = As + (stage)*256*SSTRIDE;                        \
        __nv_bfloat16* bsb = Bs + (stage)*128*SSTRIDE;                        \
        _Pragma("unroll")                                                     \
        for (int i = 0; i < 2; i++) {                                         \
            int idx = tid + 512*i, row = idx >> 2, seg = idx & 3;             \
            unsigned int sa = (unsigned int)__cvta_generic_to_shared(         \
                &asb[row*SSTRIDE + seg*8]);                                   \
            CP_ASYNC16(sa, Ag + (size_t)row*KP_ + (k0) + seg*8);              \
        }                                                                     \
        {                                                                     \
            unsigned int sb = (unsigned int)__cvta_generic_to_shared(         \
                &bsb[brow*SSTRIDE + bseg*8]);                                 \
            CP_ASYNC16(sb, Bg + (size_t)brow*KP_ + (k0) + bseg*8);            \
        }                                                                     \
        asm volatile("cp.async.commit_group;\n");                             \
    } while (0)

    ISSUE_STAGE(0, 0);
    ISSUE_STAGE(1, 32);

    for (int kt = 0; kt < nt; kt++) {
        const int stage = kt % GSTAGES;
        asm volatile("cp.async.wait_group %0;\n" :: "n"(1));
        __syncthreads();

        if (kt + 2 < nt) {
            ISSUE_STAGE((kt + 2) % GSTAGES, (kt + 2) * 32);
        }

        const __nv_bfloat16* asb = As + stage*256*SSTRIDE;
        const __nv_bfloat16* bsb = Bs + stage*128*SSTRIDE;

#pragma unroll
        for (int ks = 0; ks < 2; ks++) {
            const int k16 = ks * 16;
            // A fragments via ldmatrix.x4: m0..m3 = a0..a3
            unsigned int af[2][4];
#pragma unroll
            for (int mi = 0; mi < 2; mi++) {
                LDSM_X4(af[mi][0], af[mi][1], af[mi][2], af[mi][3],
                        &asb[(wm + mi*16 + lrow)*SSTRIDE + k16 + lcol]);
            }
            // B fragments via ldmatrix.x4 over [n][k]:
            // m0 = b0 of nj=2p, m1 = b0 of nj=2p+1, m2 = b1 of 2p, m3 = b1 of 2p+1
            unsigned int bm[4][4];
#pragma unroll
            for (int p = 0; p < 4; p++) {
                LDSM_X4(bm[p][0], bm[p][1], bm[p][2], bm[p][3],
                        &bsb[(wn + p*16 + lrow)*SSTRIDE + k16 + lcol]);
            }
#pragma unroll
            for (int mi = 0; mi < 2; mi++)
#pragma unroll
                for (int p = 0; p < 4; p++) {
                    MMA16816(c[mi][2*p],   af[mi][0], af[mi][1], af[mi][2], af[mi][3],
                             bm[p][0], bm[p][2]);
                    MMA16816(c[mi][2*p+1], af[mi][0], af[mi][1], af[mi][2], af[mi][3],
                             bm[p][1], bm[p][3]);
                }
        }
        __syncthreads();   // all reads of this stage done before it is refilled
    }
#undef ISSUE_STAGE

#pragma unroll
    for (int mi = 0; mi < 2; mi++) {
#pragma unroll
        for (int nj = 0; nj < 8; nj++) {
            int row = m0 + wm + mi*16 + (lane >> 2);
            int col = n0 + wn + nj*8 + (lane & 3)*2;
            float b0 = bias[col], b1 = bias[col+1];
            float2 v0 = { c[mi][nj][0] + b0, c[mi][nj][1] + b1 };
            float2 v1 = { c[mi][nj][2] + b0, c[mi][nj][3] + b1 };
            if (MODE == 0) {
                *(float2*)&out[(size_t)row*N + col]     = v0;
                *(float2*)&out[(size_t)(row+8)*N + col] = v1;
            } else {
                int which = col >> 10;
                int h = (col & 1023) >> 6;
                int d = col & 63;
                float* dst = (which == 0) ? g_q : ((which == 1) ? g_k : g_v);
                int b = row >> 11, t = row & 2047;
                size_t base0 = ((size_t)(b*H_ + h)*T_ + t    )*D_ + d;
                size_t base1 = ((size_t)(b*H_ + h)*T_ + t + 8)*D_ + d;
                *(float2*)&dst[base0] = v0;
                *(float2*)&dst[base1] = v1;
            }
        }
    }
}

// ---------------------------------------------------------------------------
// RoPE in place on q,k (proven).
// ---------------------------------------------------------------------------
__global__ void rope_kernel()
{
    int idx = blockIdx.x * blockDim.x + threadIdx.x;
    int d  = idx & 31;
    int t  = (idx >> 5) & (T_ - 1);
    int bh = idx >> 16;
    size_t base = ((size_t)bh * T_ + t) * D_;

    const float L2_10000_OVER_32 = 13.287712379549449f / 32.0f;
    float f = exp2f(-(float)d * L2_10000_OVER_32);
    float ang = (float)t * f;
    float s, cc;
    sincosf(ang, &s, &cc);

    float q1 = g_q[base + d], q2 = g_q[base + d + 32];
    g_q[base + d]      = q1*cc - q2*s;
    g_q[base + d + 32] = q2*cc + q1*s;
    float k1 = g_k[base + d], k2 = g_k[base + d + 32];
    g_k[base + d]      = k1*cc - k2*s;
    g_k[base + d + 32] = k2*cc + k1*s;
}

// ---------------------------------------------------------------------------
// Tensor-core causal flash attention (proven in R6, unchanged).
// ---------------------------------------------------------------------------
#define QST 136
#define KST 136
#define VST 72
#define SC_ 0.125f
#define ATTN_SMEM ((128*QST + 64*KST + 128*VST) * 2)

__global__ void __launch_bounds__(256) attn_mma()
{
    extern __shared__ __align__(16) __nv_bfloat16 smA[];
    __nv_bfloat16* Qs = smA;              // [128][QST]: cols [q_hi(64) | q_lo(64)]
    __nv_bfloat16* Ks = Qs + 128*QST;     // [64][KST]:  cols [k_hi | k_lo]
    __nv_bfloat16* Vs = Ks + 64*KST;      // [128][VST]: rows [v_hi | v_lo]

    const int qt  = (int)gridDim.x - 1 - (int)blockIdx.x;   // heavy blocks first
    const int bh  = blockIdx.y;
    const int tid = threadIdx.x;
    const int wid = tid >> 5;
    const int lane = tid & 31;
    const int lg = lane >> 2;
    const int lq = lane & 3;

    const float* qb = g_q + ((size_t)bh*T_ + qt*128)*D_;
#pragma unroll
    for (int i = 0; i < 8; i++) {
        int idx = tid + i*256;
        int r = idx >> 4, d4 = (idx & 15) << 2;
        float4 v = *(const float4*)(qb + r*64 + d4);
        float vv[4] = {v.x, v.y, v.z, v.w};
#pragma unroll
        for (int e = 0; e < 4; e += 2) {
            __nv_bfloat162 hp, lp;
            hp.x = __float2bfloat16(vv[e]);
            hp.y = __float2bfloat16(vv[e+1]);
            lp.x = __float2bfloat16(vv[e]   - __bfloat162float(hp.x));
            lp.y = __float2bfloat16(vv[e+1] - __bfloat162float(hp.y));
            *(__nv_bfloat162*)&Qs[r*QST + d4 + e]      = hp;
            *(__nv_bfloat162*)&Qs[r*QST + 64 + d4 + e] = lp;
        }
    }

    float m2[2] = {-CUDART_INF_F, -CUDART_INF_F};
    float l2[2] = {0.f, 0.f};
    float oc[8][4];
#pragma unroll
    for (int j = 0; j < 8; j++)
#pragma unroll
        for (int r = 0; r < 4; r++) oc[j][r] = 0.f;

    const int jmax = 2*qt + 1;
    for (int jt = 0; jt <= jmax; jt++) {
        __syncthreads();
        const float* kb = g_k + ((size_t)bh*T_ + jt*64)*D_;
        const float* vb = g_v + ((size_t)bh*T_ + jt*64)*D_;
#pragma unroll
        for (int i = 0; i < 4; i++) {
            int idx = tid + i*256;
            int r = idx >> 4, d4 = (idx & 15) << 2;
            float4 kv = *(const float4*)(kb + r*64 + d4);
            float4 vv = *(const float4*)(vb + r*64 + d4);
            float kk[4] = {kv.x, kv.y, kv.z, kv.w};
            float vf[4] = {vv.x, vv.y, vv.z, vv.w};
#pragma unroll
            for (int e = 0; e < 4; e += 2) {
                __nv_bfloat162 hp, lp;
                hp.x = __float2bfloat16(kk[e]);
                hp.y = __float2bfloat16(kk[e+1]);
                lp.x = __float2bfloat16(kk[e]   - __bfloat162float(hp.x));
                lp.y = __float2bfloat16(kk[e+1] - __bfloat162float(hp.y));
                *(__nv_bfloat162*)&Ks[r*KST + d4 + e]      = hp;
                *(__nv_bfloat162*)&Ks[r*KST + 64 + d4 + e] = lp;
                hp.x = __float2bfloat16(vf[e]);
                hp.y = __float2bfloat16(vf[e+1]);
                lp.x = __float2bfloat16(vf[e]   - __bfloat162float(hp.x));
                lp.y = __float2bfloat16(vf[e+1] - __bfloat162float(hp.y));
                *(__nv_bfloat162*)&Vs[r*VST + d4 + e]      = hp;
                *(__nv_bfloat162*)&Vs[(r+64)*VST + d4 + e] = lp;
            }
        }
        __syncthreads();

        float sc[8][4];
#pragma unroll
        for (int j = 0; j < 8; j++)
#pragma unroll
            for (int r = 0; r < 4; r++) sc[j][r] = 0.f;

#pragma unroll
        for (int ks = 0; ks < 12; ks++) {
            int kk4 = (ks & 3) * 16 + lq*2;
            int kcA = ((ks >= 8) ? 64 : 0) + kk4;
            int kcB = ((ks >= 4 && ks < 8) ? 64 : 0) + kk4;
            int ra = wid*16 + lg;
            unsigned int a0 = *(const unsigned int*)&Qs[ra*QST + kcA];
            unsigned int a1 = *(const unsigned int*)&Qs[(ra+8)*QST + kcA];
            unsigned int a2 = *(const unsigned int*)&Qs[ra*QST + kcA + 8];
            unsigned int a3 = *(const unsigned int*)&Qs[(ra+8)*QST + kcA + 8];
#pragma unroll
            for (int nj = 0; nj < 8; nj++) {
                unsigned int b0 = *(const unsigned int*)&Ks[(nj*8+lg)*KST + kcB];
                unsigned int b1 = *(const unsigned int*)&Ks[(nj*8+lg)*KST + kcB + 8];
                MMA16816(sc[nj], a0, a1, a2, a3, b0, b1);
            }
        }

        const bool needmask = (jt >= 2*qt);
        float rowm[2] = {-CUDART_INF_F, -CUDART_INF_F};
#pragma unroll
        for (int nj = 0; nj < 8; nj++) {
            if (needmask) {
                int kg  = jt*64 + nj*8 + lq*2;
                int qr0 = qt*128 + wid*16 + lg;
#pragma unroll
                for (int e = 0; e < 4; e++) {
                    if (kg + (e & 1) > qr0 + (e >> 1)*8) sc[nj][e] = -CUDART_INF_F;
                }
            }
            rowm[0] = fmaxf(rowm[0], fmaxf(sc[nj][0], sc[nj][1]));
            rowm[1] = fmaxf(rowm[1], fmaxf(sc[nj][2], sc[nj][3]));
        }
#pragma unroll
        for (int off = 1; off <= 2; off <<= 1) {
            rowm[0] = fmaxf(rowm[0], __shfl_xor_sync(0xffffffffu, rowm[0], off));
            rowm[1] = fmaxf(rowm[1], __shfl_xor_sync(0xffffffffu, rowm[1], off));
        }
        float corr[2];
#pragma unroll
        for (int h = 0; h < 2; h++) {
            float mn = fmaxf(m2[h], rowm[h]);
            corr[h] = __expf((m2[h] - mn) * SC_);
            m2[h] = mn;
        }
        float rs[2] = {0.f, 0.f};
        unsigned int ph[8][2], pl[8][2];
#pragma unroll
        for (int nj = 0; nj < 8; nj++) {
            float p0 = __expf((sc[nj][0] - m2[0]) * SC_);
            float p1 = __expf((sc[nj][1] - m2[0]) * SC_);
            float p2 = __expf((sc[nj][2] - m2[1]) * SC_);
            float p3 = __expf((sc[nj][3] - m2[1]) * SC_);
            rs[0] += p0 + p1;
            rs[1] += p2 + p3;
            __nv_bfloat162 h01, h23, l01, l23;
            h01.x = __float2bfloat16(p0); h01.y = __float2bfloat16(p1);
            l01.x = __float2bfloat16(p0 - __bfloat162float(h01.x));
            l01.y = __float2bfloat16(p1 - __bfloat162float(h01.y));
            h23.x = __float2bfloat16(p2); h23.y = __float2bfloat16(p3);
            l23.x = __float2bfloat16(p2 - __bfloat162float(h23.x));
            l23.y = __float2bfloat16(p3 - __bfloat162float(h23.y));
            ph[nj][0] = *(unsigned int*)&h01;
            ph[nj][1] = *(unsigned int*)&h23;
            pl[nj][0] = *(unsigned int*)&l01;
            pl[nj][1] = *(unsigned int*)&l23;
        }
#pragma unroll
        for (int off = 1; off <= 2; off <<= 1) {
            rs[0] += __shfl_xor_sync(0xffffffffu, rs[0], off);
            rs[1] += __shfl_xor_sync(0xffffffffu, rs[1], off);
        }
#pragma unroll
        for (int h = 0; h < 2; h++) l2[h] = l2[h]*corr[h] + rs[h];
#pragma unroll
        for (int nj = 0; nj < 8; nj++) {
            oc[nj][0] *= corr[0]; oc[nj][1] *= corr[0];
            oc[nj][2] *= corr[1]; oc[nj][3] *= corr[1];
        }

#pragma unroll
        for (int ks = 0; ks < 12; ks++) {
            int kk = ks & 3;
            unsigned int a0, a1, a2, a3;
            if (ks < 8) {
                a0 = ph[2*kk][0]; a1 = ph[2*kk][1];
                a2 = ph[2*kk+1][0]; a3 = ph[2*kk+1][1];
            } else {
                a0 = pl[2*kk][0]; a1 = pl[2*kk][1];
                a2 = pl[2*kk+1][0]; a3 = pl[2*kk+1][1];
            }
            int kcV = ((ks >= 4 && ks < 8) ? 64 : 0) + kk*16;
            int g = lane >> 3, rr = lane & 7;
#pragma unroll
            for (int njp = 0; njp < 4; njp++) {
                unsigned int addr = (unsigned int)__cvta_generic_to_shared(
                    &Vs[(kcV + rr + (g & 1)*8)*VST + njp*16 + (g >> 1)*8]);
                unsigned int b0, b1, b2, b3;
                asm volatile(
                    "ldmatrix.sync.aligned.m8n8.x4.trans.shared.b16 {%0,%1,%2,%3}, [%4];\n"
                    : "=r"(b0), "=r"(b1), "=r"(b2), "=r"(b3) : "r"(addr));
                MMA16816(oc[njp*2],   a0, a1, a2, a3, b0, b1);
                MMA16816(oc[njp*2+1], a0, a1, a2, a3, b2, b3);
            }
        }
    }

    int b = bh >> 4, h = bh & 15;
#pragma unroll
    for (int half = 0; half < 2; half++) {
        float inv = 1.0f / l2[half];
        int trow = qt*128 + wid*16 + lg + half*8;
        size_t rowbase = ((size_t)b*T_ + trow) * (size_t)KP_;
        int c0 = h*64 + lq*2;
#pragma unroll
        for (int nj = 0; nj < 8; nj++) {
            float y0 = oc[nj][half*2]   * inv;
            float y1 = oc[nj][half*2+1] * inv;
            __nv_bfloat162 hp, lp;
            hp.x = __float2bfloat16(y0);
            hp.y = __float2bfloat16(y1);
            lp.x = __float2bfloat16(y0 - __bfloat162float(hp.x));
            lp.y = __float2bfloat16(y1 - __bfloat162float(hp.y));
            int c = c0 + nj*8;
            *(__nv_bfloat162*)&g_ys[rowbase + c]        = hp;
            *(__nv_bfloat162*)&g_ys[rowbase + 1024 + c] = hp;
            *(__nv_bfloat162*)&g_ys[rowbase + 2048 + c] = lp;
        }
    }
}

// ---------------------------------------------------------------------------
extern "C" void kernel_launch(void* const* d_in, const int* in_sizes, int n_in,
                              void* d_out, int out_size)
{
    const float* x      = (const float*)d_in[0];
    const float* W_attn = (const float*)d_in[1];
    const float* b_attn = (const float*)d_in[2];
    const float* W_proj = (const float*)d_in[3];
    const float* b_proj = (const float*)d_in[4];
    float* out = (float*)d_out;

    split_x_kernel<<<(M_*C_/4 + 255)/256, 256>>>(x);
    split_w_kernel<<<(3*C_*C_/4 + 255)/256, 256>>>(W_attn);
    split_wp_kernel<<<(C_*C_/4 + 255)/256, 256>>>(W_proj);

    cudaFuncSetAttribute(mma_gemm<1>, cudaFuncAttributeMaxDynamicSharedMemorySize, GEMM_SMEM);
    cudaFuncSetAttribute(mma_gemm<0>, cudaFuncAttributeMaxDynamicSharedMemorySize, GEMM_SMEM);

    mma_gemm<1><<<dim3(3*C_/128, M_/256), 512, GEMM_SMEM>>>(b_attn, nullptr);

    rope_kernel<<<(B_*H_*T_*32)/256, 256>>>();

    cudaFuncSetAttribute(attn_mma, cudaFuncAttributeMaxDynamicSharedMemorySize, ATTN_SMEM);
    attn_mma<<<dim3(T_/128, B_*H_), 256, ATTN_SMEM>>>();

    mma_gemm<0><<<dim3(C_/128, M_/256), 512, GEMM_SMEM>>>(b_proj, out);
}

// round 9
// speedup vs baseline: 2.0557x; 1.0262x over previous
#include <cuda_runtime.h>
#include <cuda_bf16.h>
#include <math_constants.h>
#include <cstdint>

// Problem constants
#define B_  2
#define T_  2048
#define C_  1024
#define H_  16
#define D_  64
#define M_  (B_*T_)          // 4096 rows
#define BHTD (B_*H_*T_*D_)
#define KP_ (3*C_)           // 3072 split-K

// Scratch (device globals, referenced directly from kernels)
__device__ float g_q[BHTD];
__device__ float g_k[BHTD];
__device__ __nv_bfloat16 g_qs[(size_t)BHTD*2];       // q split [bh][t][hi64|lo64]
__device__ __nv_bfloat16 g_ks[(size_t)BHTD*2];       // k split
__device__ __nv_bfloat16 g_vs[(size_t)BHTD*2];       // v split
__device__ __nv_bfloat16 g_xs[(size_t)M_ * KP_];     // x split      [4096,3072]
__device__ __nv_bfloat16 g_ws[(size_t)3*C_ * KP_];   // W_attn split  [3072,3072]
__device__ __nv_bfloat16 g_ys[(size_t)M_ * KP_];     // y split       [4096,3072]
__device__ __nv_bfloat16 g_wps[(size_t)C_ * KP_];    // W_proj split  [1024,3072]

// ---------------------------------------------------------------------------
// fp32 -> bf16 hi/lo splits packed along K'=3K=3072.
// A-side: [hi, hi, lo];  B-side: [hi, lo, hi]  =>  hi*hi + hi*lo + lo*hi
// ---------------------------------------------------------------------------
__global__ void split_x_kernel(const float* __restrict__ src)
{
    int idx = blockIdx.x * blockDim.x + threadIdx.x;
    if (idx >= M_*C_/4) return;
    float4 v = ((const float4*)src)[idx];
    int r = idx >> 8;
    int k = (idx & 255) * 4;
    float vv[4] = {v.x, v.y, v.z, v.w};
    size_t base = (size_t)r * KP_ + k;
#pragma unroll
    for (int i = 0; i < 4; i++) {
        __nv_bfloat16 hi = __float2bfloat16(vv[i]);
        __nv_bfloat16 lo = __float2bfloat16(vv[i] - __bfloat162float(hi));
        g_xs[base + i]        = hi;
        g_xs[base + C_ + i]   = hi;
        g_xs[base + 2*C_ + i] = lo;
    }
}

__global__ void split_w_kernel(const float* __restrict__ src)
{
    int idx = blockIdx.x * blockDim.x + threadIdx.x;
    if (idx >= 3*C_*C_/4) return;
    float4 v = ((const float4*)src)[idx];
    int r = idx >> 8;
    int k = (idx & 255) * 4;
    float vv[4] = {v.x, v.y, v.z, v.w};
    size_t base = (size_t)r * KP_ + k;
#pragma unroll
    for (int i = 0; i < 4; i++) {
        __nv_bfloat16 hi = __float2bfloat16(vv[i]);
        __nv_bfloat16 lo = __float2bfloat16(vv[i] - __bfloat162float(hi));
        g_ws[base + i]        = hi;
        g_ws[base + C_ + i]   = lo;
        g_ws[base + 2*C_ + i] = hi;
    }
}

__global__ void split_wp_kernel(const float* __restrict__ src)
{
    int idx = blockIdx.x * blockDim.x + threadIdx.x;
    if (idx >= C_*C_/4) return;
    float4 v = ((const float4*)src)[idx];
    int r = idx >> 8;
    int k = (idx & 255) * 4;
    float vv[4] = {v.x, v.y, v.z, v.w};
    size_t base = (size_t)r * KP_ + k;
#pragma unroll
    for (int i = 0; i < 4; i++) {
        __nv_bfloat16 hi = __float2bfloat16(vv[i]);
        __nv_bfloat16 lo = __float2bfloat16(vv[i] - __bfloat162float(hi));
        g_wps[base + i]        = hi;
        g_wps[base + C_ + i]   = lo;
        g_wps[base + 2*C_ + i] = hi;
    }
}

// ---------------------------------------------------------------------------
// Tensor-core GEMM over pre-split operands.
// 256x128 tile, 512 threads (16 warps: 8 M x 2 N, warp 32x64),
// 4-stage cp.async pipeline (single sync per tile), ldmatrix.x4 fragments.
// MODE 1: g_xs * g_ws^T + b_attn -> q,k fp32 [B,H,T,D]; v split bf16 g_vs
// MODE 0: g_ys * g_wps^T + b_proj -> out row-major [M,1024]
// ---------------------------------------------------------------------------
#define SSTRIDE 40
#define GSTAGES 4
#define GEMM_SMEM ((GSTAGES*(256+128)*SSTRIDE)*2)

#define MMA16816(C4, A0,A1,A2,A3, B0,B1)                                      \
    asm volatile(                                                             \
        "mma.sync.aligned.m16n8k16.row.col.f32.bf16.bf16.f32 "                \
        "{%0,%1,%2,%3}, {%4,%5,%6,%7}, {%8,%9}, {%0,%1,%2,%3};\n"             \
        : "+f"((C4)[0]), "+f"((C4)[1]), "+f"((C4)[2]), "+f"((C4)[3])          \
        : "r"(A0), "r"(A1), "r"(A2), "r"(A3), "r"(B0), "r"(B1))

#define LDSM_X4(R0,R1,R2,R3, ptr)                                             \
    do {                                                                      \
        unsigned int _a = (unsigned int)__cvta_generic_to_shared(ptr);        \
        asm volatile(                                                         \
            "ldmatrix.sync.aligned.m8n8.x4.shared.b16 {%0,%1,%2,%3}, [%4];\n" \
            : "=r"(R0), "=r"(R1), "=r"(R2), "=r"(R3) : "r"(_a));              \
    } while (0)

#define CP_ASYNC16(smem_u32, gptr)                                            \
    asm volatile("cp.async.cg.shared.global [%0], [%1], 16;\n"                \
                 :: "r"(smem_u32), "l"(gptr))

template<int MODE>
__global__ void __launch_bounds__(512) mma_gemm(
    const float* __restrict__ bias, float* __restrict__ out)
{
    const __nv_bfloat16* A  = (MODE == 1) ? g_xs : g_ys;
    const __nv_bfloat16* Bw = (MODE == 1) ? g_ws : g_wps;
    const int N = (MODE == 1) ? 3*C_ : C_;

    extern __shared__ __align__(16) __nv_bfloat16 gsm[];
    __nv_bfloat16* As = gsm;                          // [GSTAGES][256*SSTRIDE]
    __nv_bfloat16* Bs = gsm + GSTAGES*256*SSTRIDE;    // [GSTAGES][128*SSTRIDE]

    const int tid  = threadIdx.x;
    const int wid  = tid >> 5;
    const int lane = tid & 31;
    const int m0 = blockIdx.y * 256;
    const int n0 = blockIdx.x * 128;
    const int wm = (wid >> 1) * 32;
    const int wn = (wid & 1) * 64;
    const int lrow = lane & 15;
    const int lcol = (lane >> 4) << 3;

    const __nv_bfloat16* Ag = A  + (size_t)m0 * KP_;
    const __nv_bfloat16* Bg = Bw + (size_t)n0 * KP_;

    const int brow = tid >> 2, bseg = tid & 3;

    float c[2][8][4];
#pragma unroll
    for (int i = 0; i < 2; i++)
#pragma unroll
        for (int j = 0; j < 8; j++)
#pragma unroll
            for (int r = 0; r < 4; r++) c[i][j][r] = 0.f;

    const int nt = KP_ / 32;   // 96

#define ISSUE_STAGE(stage, k0)                                                \
    do {                                                                      \
        __nv_bfloat16* asb = As + (stage)*256*SSTRIDE;                        \
        __nv_bfloat16* bsb = Bs + (stage)*128*SSTRIDE;                        \
        _Pragma("unroll")                                                     \
        for (int i = 0; i < 2; i++) {                                         \
            int idx = tid + 512*i, row = idx >> 2, seg = idx & 3;             \
            unsigned int sa = (unsigned int)__cvta_generic_to_shared(         \
                &asb[row*SSTRIDE + seg*8]);                                   \
            CP_ASYNC16(sa, Ag + (size_t)row*KP_ + (k0) + seg*8);              \
        }                                                                     \
        {                                                                     \
            unsigned int sb = (unsigned int)__cvta_generic_to_shared(         \
                &bsb[brow*SSTRIDE + bseg*8]);                                 \
            CP_ASYNC16(sb, Bg + (size_t)brow*KP_ + (k0) + bseg*8);            \
        }                                                                     \
        asm volatile("cp.async.commit_group;\n");                             \
    } while (0)

    ISSUE_STAGE(0, 0);
    ISSUE_STAGE(1, 32);
    ISSUE_STAGE(2, 64);

    for (int kt = 0; kt < nt; kt++) {
        const int stage = kt % GSTAGES;
        asm volatile("cp.async.wait_group %0;\n" :: "n"(2));
        __syncthreads();   // data for stage kt visible; prior reads of (kt+3)%4 done

        if (kt + 3 < nt) {
            ISSUE_STAGE((kt + 3) % GSTAGES, (kt + 3) * 32);
        }

        const __nv_bfloat16* asb = As + stage*256*SSTRIDE;
        const __nv_bfloat16* bsb = Bs + stage*128*SSTRIDE;

#pragma unroll
        for (int ks = 0; ks < 2; ks++) {
            const int k16 = ks * 16;
            unsigned int af[2][4];
#pragma unroll
            for (int mi = 0; mi < 2; mi++) {
                LDSM_X4(af[mi][0], af[mi][1], af[mi][2], af[mi][3],
                        &asb[(wm + mi*16 + lrow)*SSTRIDE + k16 + lcol]);
            }
            unsigned int bm[4][4];
#pragma unroll
            for (int p = 0; p < 4; p++) {
                LDSM_X4(bm[p][0], bm[p][1], bm[p][2], bm[p][3],
                        &bsb[(wn + p*16 + lrow)*SSTRIDE + k16 + lcol]);
            }
#pragma unroll
            for (int mi = 0; mi < 2; mi++)
#pragma unroll
                for (int p = 0; p < 4; p++) {
                    MMA16816(c[mi][2*p],   af[mi][0], af[mi][1], af[mi][2], af[mi][3],
                             bm[p][0], bm[p][2]);
                    MMA16816(c[mi][2*p+1], af[mi][0], af[mi][1], af[mi][2], af[mi][3],
                             bm[p][1], bm[p][3]);
                }
        }
    }
#undef ISSUE_STAGE

#pragma unroll
    for (int mi = 0; mi < 2; mi++) {
#pragma unroll
        for (int nj = 0; nj < 8; nj++) {
            int row = m0 + wm + mi*16 + (lane >> 2);
            int col = n0 + wn + nj*8 + (lane & 3)*2;
            float b0 = bias[col], b1 = bias[col+1];
            float2 v0 = { c[mi][nj][0] + b0, c[mi][nj][1] + b1 };
            float2 v1 = { c[mi][nj][2] + b0, c[mi][nj][3] + b1 };
            if (MODE == 0) {
                *(float2*)&out[(size_t)row*N + col]     = v0;
                *(float2*)&out[(size_t)(row+8)*N + col] = v1;
            } else {
                int which = col >> 10;
                int h = (col & 1023) >> 6;
                int d = col & 63;
                int b = row >> 11, t = row & 2047;
                if (which == 2) {
                    // V: write split bf16 [hi64|lo64] rows directly
                    size_t vb0 = ((size_t)(b*H_ + h)*T_ + t    )*128 + d;
                    size_t vb1 = ((size_t)(b*H_ + h)*T_ + t + 8)*128 + d;
                    __nv_bfloat162 h0, l0, h1, l1;
                    h0.x = __float2bfloat16(v0.x);
                    h0.y = __float2bfloat16(v0.y);
                    l0.x = __float2bfloat16(v0.x - __bfloat162float(h0.x));
                    l0.y = __float2bfloat16(v0.y - __bfloat162float(h0.y));
                    h1.x = __float2bfloat16(v1.x);
                    h1.y = __float2bfloat16(v1.y);
                    l1.x = __float2bfloat16(v1.x - __bfloat162float(h1.x));
                    l1.y = __float2bfloat16(v1.y - __bfloat162float(h1.y));
                    *(__nv_bfloat162*)&g_vs[vb0]      = h0;
                    *(__nv_bfloat162*)&g_vs[vb0 + 64] = l0;
                    *(__nv_bfloat162*)&g_vs[vb1]      = h1;
                    *(__nv_bfloat162*)&g_vs[vb1 + 64] = l1;
                } else {
                    float* dst = (which == 0) ? g_q : g_k;
                    size_t base0 = ((size_t)(b*H_ + h)*T_ + t    )*D_ + d;
                    size_t base1 = ((size_t)(b*H_ + h)*T_ + t + 8)*D_ + d;
                    *(float2*)&dst[base0] = v0;
                    *(float2*)&dst[base1] = v1;
                }
            }
        }
    }
}

// ---------------------------------------------------------------------------
// RoPE on q,k (fp32 in) -> split bf16 [hi64|lo64] rows out (g_qs, g_ks).
// ---------------------------------------------------------------------------
__global__ void rope_kernel()
{
    int idx = blockIdx.x * blockDim.x + threadIdx.x;
    int d  = idx & 31;
    int t  = (idx >> 5) & (T_ - 1);
    int bh = idx >> 16;
    size_t base = ((size_t)bh * T_ + t) * D_;
    size_t ob   = ((size_t)bh * T_ + t) * 128;

    const float L2_10000_OVER_32 = 13.287712379549449f / 32.0f;
    float f = exp2f(-(float)d * L2_10000_OVER_32);
    float ang = (float)t * f;
    float s, cc;
    sincosf(ang, &s, &cc);

    float q1 = g_q[base + d], q2 = g_q[base + d + 32];
    float o1 = q1*cc - q2*s;
    float o2 = q2*cc + q1*s;
    __nv_bfloat16 h1 = __float2bfloat16(o1);
    __nv_bfloat16 h2 = __float2bfloat16(o2);
    g_qs[ob + d]           = h1;
    g_qs[ob + d + 32]      = h2;
    g_qs[ob + 64 + d]      = __float2bfloat16(o1 - __bfloat162float(h1));
    g_qs[ob + 64 + d + 32] = __float2bfloat16(o2 - __bfloat162float(h2));

    float k1 = g_k[base + d], k2 = g_k[base + d + 32];
    o1 = k1*cc - k2*s;
    o2 = k2*cc + k1*s;
    h1 = __float2bfloat16(o1);
    h2 = __float2bfloat16(o2);
    g_ks[ob + d]           = h1;
    g_ks[ob + d + 32]      = h2;
    g_ks[ob + 64 + d]      = __float2bfloat16(o1 - __bfloat162float(h1));
    g_ks[ob + 64 + d + 32] = __float2bfloat16(o2 - __bfloat162float(h2));
}

// ---------------------------------------------------------------------------
// Tensor-core causal flash attention over pre-split bf16 q/k/v.
// Inner loop: byte-copies + ldmatrix + MMA only (no conversions).
// ---------------------------------------------------------------------------
#define QST 136
#define KST 136
#define VST 72
#define SC_ 0.125f
#define ATTN_SMEM ((128*QST + 64*KST + 128*VST) * 2)

__global__ void __launch_bounds__(256) attn_mma()
{
    extern __shared__ __align__(16) __nv_bfloat16 smA[];
    __nv_bfloat16* Qs = smA;              // [128][QST]: [q_hi(64) | q_lo(64)]
    __nv_bfloat16* Ks = Qs + 128*QST;     // [64][KST]:  [k_hi | k_lo]
    __nv_bfloat16* Vs = Ks + 64*KST;      // [128][VST]: rows 0-63 v_hi, 64-127 v_lo

    const int qt  = (int)gridDim.x - 1 - (int)blockIdx.x;   // heavy blocks first
    const int bh  = blockIdx.y;
    const int tid = threadIdx.x;
    const int wid = tid >> 5;
    const int lane = tid & 31;
    const int lg = lane >> 2;
    const int lq = lane & 3;
    const int lrow = lane & 15;
    const int lcol = (lane >> 4) << 3;

    const __nv_bfloat16* qsrc = g_qs + ((size_t)bh*T_ + qt*128)*128;
#pragma unroll
    for (int i = 0; i < 8; i++) {
        int idx = tid + i*256;
        int r = idx >> 4, u = (idx & 15) * 8;
        *(uint4*)&Qs[r*QST + u] = *(const uint4*)&qsrc[r*128 + u];
    }

    float m2[2] = {-CUDART_INF_F, -CUDART_INF_F};
    float l2[2] = {0.f, 0.f};
    float oc[8][4];
#pragma unroll
    for (int j = 0; j < 8; j++)
#pragma unroll
        for (int r = 0; r < 4; r++) oc[j][r] = 0.f;

    const int jmax = 2*qt + 1;
    for (int jt = 0; jt <= jmax; jt++) {
        __syncthreads();
        const __nv_bfloat16* ksrc = g_ks + ((size_t)bh*T_ + jt*64)*128;
        const __nv_bfloat16* vsrc = g_vs + ((size_t)bh*T_ + jt*64)*128;
#pragma unroll
        for (int i = 0; i < 4; i++) {
            int idx = tid + i*256;
            int r = idx >> 4, u = idx & 15;
            *(uint4*)&Ks[r*KST + u*8] = *(const uint4*)&ksrc[r*128 + u*8];
            if (u < 8)
                *(uint4*)&Vs[r*VST + u*8] = *(const uint4*)&vsrc[r*128 + u*8];
            else
                *(uint4*)&Vs[(r+64)*VST + (u-8)*8] = *(const uint4*)&vsrc[r*128 + u*8];
        }
        __syncthreads();

        // ---- S = Q K^T (16x64 per warp, aliased hi/lo segments) ----
        float sc[8][4];
#pragma unroll
        for (int j = 0; j < 8; j++)
#pragma unroll
            for (int r = 0; r < 4; r++) sc[j][r] = 0.f;

#pragma unroll
        for (int ks = 0; ks < 12; ks++) {
            int kk16 = (ks & 3) * 16;
            int Aoff = (ks >= 8) ? 64 : 0;                 // Q: [hi,hi,lo]
            int Boff = (ks >= 4 && ks < 8) ? 64 : 0;       // K: [hi,lo,hi]
            unsigned int af[4];
            LDSM_X4(af[0], af[1], af[2], af[3],
                    &Qs[(wid*16 + lrow)*QST + Aoff + kk16 + lcol]);
#pragma unroll
            for (int p = 0; p < 4; p++) {
                unsigned int bm0, bm1, bm2, bm3;
                LDSM_X4(bm0, bm1, bm2, bm3,
                        &Ks[(p*16 + lrow)*KST + Boff + kk16 + lcol]);
                MMA16816(sc[2*p],   af[0], af[1], af[2], af[3], bm0, bm2);
                MMA16816(sc[2*p+1], af[0], af[1], af[2], af[3], bm1, bm3);
            }
        }

        // ---- mask + online softmax ----
        const bool needmask = (jt >= 2*qt);
        float rowm[2] = {-CUDART_INF_F, -CUDART_INF_F};
#pragma unroll
        for (int nj = 0; nj < 8; nj++) {
            if (needmask) {
                int kg  = jt*64 + nj*8 + lq*2;
                int qr0 = qt*128 + wid*16 + lg;
#pragma unroll
                for (int e = 0; e < 4; e++) {
                    if (kg + (e & 1) > qr0 + (e >> 1)*8) sc[nj][e] = -CUDART_INF_F;
                }
            }
            rowm[0] = fmaxf(rowm[0], fmaxf(sc[nj][0], sc[nj][1]));
            rowm[1] = fmaxf(rowm[1], fmaxf(sc[nj][2], sc[nj][3]));
        }
#pragma unroll
        for (int off = 1; off <= 2; off <<= 1) {
            rowm[0] = fmaxf(rowm[0], __shfl_xor_sync(0xffffffffu, rowm[0], off));
            rowm[1] = fmaxf(rowm[1], __shfl_xor_sync(0xffffffffu, rowm[1], off));
        }
        float corr[2];
#pragma unroll
        for (int h = 0; h < 2; h++) {
            float mn = fmaxf(m2[h], rowm[h]);
            corr[h] = __expf((m2[h] - mn) * SC_);
            m2[h] = mn;
        }
        float rs[2] = {0.f, 0.f};
        unsigned int ph[8][2], pl[8][2];
#pragma unroll
        for (int nj = 0; nj < 8; nj++) {
            float p0 = __expf((sc[nj][0] - m2[0]) * SC_);
            float p1 = __expf((sc[nj][1] - m2[0]) * SC_);
            float p2 = __expf((sc[nj][2] - m2[1]) * SC_);
            float p3 = __expf((sc[nj][3] - m2[1]) * SC_);
            rs[0] += p0 + p1;
            rs[1] += p2 + p3;
            __nv_bfloat162 h01, h23, l01, l23;
            h01.x = __float2bfloat16(p0); h01.y = __float2bfloat16(p1);
            l01.x = __float2bfloat16(p0 - __bfloat162float(h01.x));
            l01.y = __float2bfloat16(p1 - __bfloat162float(h01.y));
            h23.x = __float2bfloat16(p2); h23.y = __float2bfloat16(p3);
            l23.x = __float2bfloat16(p2 - __bfloat162float(h23.x));
            l23.y = __float2bfloat16(p3 - __bfloat162float(h23.y));
            ph[nj][0] = *(unsigned int*)&h01;
            ph[nj][1] = *(unsigned int*)&h23;
            pl[nj][0] = *(unsigned int*)&l01;
            pl[nj][1] = *(unsigned int*)&l23;
        }
#pragma unroll
        for (int off = 1; off <= 2; off <<= 1) {
            rs[0] += __shfl_xor_sync(0xffffffffu, rs[0], off);
            rs[1] += __shfl_xor_sync(0xffffffffu, rs[1], off);
        }
#pragma unroll
        for (int h = 0; h < 2; h++) l2[h] = l2[h]*corr[h] + rs[h];
#pragma unroll
        for (int nj = 0; nj < 8; nj++) {
            oc[nj][0] *= corr[0]; oc[nj][1] *= corr[0];
            oc[nj][2] *= corr[1]; oc[nj][3] *= corr[1];
        }

        // ---- O += P V ----
#pragma unroll
        for (int ks = 0; ks < 12; ks++) {
            int kk = ks & 3;
            unsigned int a0, a1, a2, a3;
            if (ks < 8) {
                a0 = ph[2*kk][0]; a1 = ph[2*kk][1];
                a2 = ph[2*kk+1][0]; a3 = ph[2*kk+1][1];
            } else {
                a0 = pl[2*kk][0]; a1 = pl[2*kk][1];
                a2 = pl[2*kk+1][0]; a3 = pl[2*kk+1][1];
            }
            int kcV = ((ks >= 4 && ks < 8) ? 64 : 0) + kk*16;   // V rows: hi 0-63, lo 64-127
            int g = lane >> 3, rr = lane & 7;
#pragma unroll
            for (int njp = 0; njp < 4; njp++) {
                unsigned int addr = (unsigned int)__cvta_generic_to_shared(
                    &Vs[(kcV + rr + (g & 1)*8)*VST + njp*16 + (g >> 1)*8]);
                unsigned int b0, b1, b2, b3;
                asm volatile(
                    "ldmatrix.sync.aligned.m8n8.x4.trans.shared.b16 {%0,%1,%2,%3}, [%4];\n"
                    : "=r"(b0), "=r"(b1), "=r"(b2), "=r"(b3) : "r"(addr));
                MMA16816(oc[njp*2],   a0, a1, a2, a3, b0, b1);
                MMA16816(oc[njp*2+1], a0, a1, a2, a3, b2, b3);
            }
        }
    }

    // ---- epilogue: normalize, write split [hi|hi|lo] into g_ys ----
    int b = bh >> 4, h = bh & 15;
#pragma unroll
    for (int half = 0; half < 2; half++) {
        float inv = 1.0f / l2[half];
        int trow = qt*128 + wid*16 + lg + half*8;
        size_t rowbase = ((size_t)b*T_ + trow) * (size_t)KP_;
        int c0 = h*64 + lq*2;
#pragma unroll
        for (int nj = 0; nj < 8; nj++) {
            float y0 = oc[nj][half*2]   * inv;
            float y1 = oc[nj][half*2+1] * inv;
            __nv_bfloat162 hp, lp;
            hp.x = __float2bfloat16(y0);
            hp.y = __float2bfloat16(y1);
            lp.x = __float2bfloat16(y0 - __bfloat162float(hp.x));
            lp.y = __float2bfloat16(y1 - __bfloat162float(hp.y));
            int c = c0 + nj*8;
            *(__nv_bfloat162*)&g_ys[rowbase + c]        = hp;
            *(__nv_bfloat162*)&g_ys[rowbase + 1024 + c] = hp;
            *(__nv_bfloat162*)&g_ys[rowbase + 2048 + c] = lp;
        }
    }
}

// ---------------------------------------------------------------------------
extern "C" void kernel_launch(void* const* d_in, const int* in_sizes, int n_in,
                              void* d_out, int out_size)
{
    const float* x      = (const float*)d_in[0];
    const float* W_attn = (const float*)d_in[1];
    const float* b_attn = (const float*)d_in[2];
    const float* W_proj = (const float*)d_in[3];
    const float* b_proj = (const float*)d_in[4];
    float* out = (float*)d_out;

    split_x_kernel<<<(M_*C_/4 + 255)/256, 256>>>(x);
    split_w_kernel<<<(3*C_*C_/4 + 255)/256, 256>>>(W_attn);
    split_wp_kernel<<<(C_*C_/4 + 255)/256, 256>>>(W_proj);

    cudaFuncSetAttribute(mma_gemm<1>, cudaFuncAttributeMaxDynamicSharedMemorySize, GEMM_SMEM);
    cudaFuncSetAttribute(mma_gemm<0>, cudaFuncAttributeMaxDynamicSharedMemorySize, GEMM_SMEM);

    mma_gemm<1><<<dim3(3*C_/128, M_/256), 512, GEMM_SMEM>>>(b_attn, nullptr);

    rope_kernel<<<(B_*H_*T_*32)/256, 256>>>();

    cudaFuncSetAttribute(attn_mma, cudaFuncAttributeMaxDynamicSharedMemorySize, ATTN_SMEM);
    attn_mma<<<dim3(T_/128, B_*H_), 256, ATTN_SMEM>>>();

    mma_gemm<0><<<dim3(C_/128, M_/256), 512, GEMM_SMEM>>>(b_proj, out);
}